// round 14
// baseline (speedup 1.0000x reference)
#include <cuda_runtime.h>
#include <math.h>

#define DN   128
#define HK   65
#define BN   4
#define TN   2
#define GN   125
#define PERB (TN*GN)      // 250
#define NBTG (BN*PERB)    // 1000
#define WIN  24
#define H0   52
#define KT   9            // ceil(65/8) kx tiles
#define CP   130          // padded column stride for tile kernels
#define FCB  33           // blocks for fc premultiply: ceil(4*128*65/1024)

// ---------------- scratch (static device memory; no allocation) ----------------
__device__ float2 g_vf[DN*DN*HK];       // vol rfft intermediate (8.5 MB)
__device__ float4 g_vf4[DN*DN*HK];      // final vol rfft, x-pair packed (17 MB)
__device__ float2 g_fimg[BN*DN*HK];     // image rffts, y fftshifted
__device__ float2 g_fc[BN*DN*HK];       // ctf*fimg*sign*alpha, precombined
__device__ float2 g_G1[NBTG*DN*WIN];    // stage-1 results (24.6 MB)
__device__ float  g_corr[NBTG];
__device__ int    g_argm[NBTG];

__device__ __forceinline__ float2 cmulf(float2 a, float2 b){
    return make_float2(a.x*b.x - a.y*b.y, a.x*b.y + a.y*b.x);
}
__device__ __forceinline__ float2 cadd(float2 a, float2 b){ return make_float2(a.x+b.x, a.y+b.y); }
__device__ __forceinline__ float2 csub(float2 a, float2 b){ return make_float2(a.x-b.x, a.y-b.y); }
__device__ __forceinline__ int rev7(int p){ return (int)(__brev((unsigned)p) >> 25); }

__device__ __forceinline__ void make_tw(float2* Ef, int tid){
    if (tid < 128){
        float s, c;
        sincosf(-6.283185307179586f * (float)tid * (1.0f/128.0f), &s, &c);
        Ef[tid] = make_float2(c, s);
    }
}
__device__ __forceinline__ void make_twi(float2* Ei, int tid){
    if (tid < 128){
        float s, c;
        sincosf(6.283185307179586f * (float)tid * (1.0f/128.0f), &s, &c);
        Ei[tid] = make_float2(c, s);
    }
}

// shfl-xor DIF butterfly
__device__ __forceinline__ void bfx(float2& r, int mask, float2 tw, int lane){
    float ox = __shfl_xor_sync(0xffffffffu, r.x, mask);
    float oy = __shfl_xor_sync(0xffffffffu, r.y, mask);
    if ((lane & mask) == 0){ r.x += ox; r.y += oy; }
    else { float ux = ox - r.x, uy = oy - r.y; r = make_float2(ux*tw.x - uy*tw.y, ux*tw.y + uy*tw.x); }
}
__device__ __forceinline__ void bf1(float2& r, int lane){
    float ox = __shfl_xor_sync(0xffffffffu, r.x, 1);
    float oy = __shfl_xor_sync(0xffffffffu, r.y, 1);
    if ((lane & 1) == 0){ r.x += ox; r.y += oy; }
    else { r.x = ox - r.x; r.y = oy - r.y; }
}

// ---------------- warp-local smem 128-pt FFT (volume/image passes) -----------
__device__ __forceinline__ void fft128_w32(float2* col, const float2* Ef, int lane){
    for (int shift = 6; shift >= 0; shift--){
        int half = 1 << shift;
        int twsh = 6 - shift;
        #pragma unroll
        for (int k = 0; k < 2; k++){
            int bf   = lane + k*32;
            int j    = bf & (half - 1);
            int grp  = bf >> shift;
            int base = (grp << (shift + 1)) + j;
            float2 u = col[base];
            float2 v = col[base + half];
            float2 d = make_float2(u.x - v.x, u.y - v.y);
            col[base]        = make_float2(u.x + v.x, u.y + v.y);
            col[base + half] = cmulf(d, Ef[j << twsh]);
        }
        __syncwarp();
    }
    float2 r[4];
    #pragma unroll
    for (int k = 0; k < 4; k++) r[k] = col[lane + k*32];
    __syncwarp();
    #pragma unroll
    for (int k = 0; k < 4; k++){
        int y = lane + k*32;
        col[rev7(y)] = r[k];
    }
    __syncwarp();
}

// ---------------- pass 1: row rffts (vol rows + img rows), warp-per-row ------
__global__ void __launch_bounds__(256) kPre(const float* __restrict__ vol,
                                            const float* __restrict__ imgs){
    __shared__ float2 ws[8][128];
    __shared__ float2 Ef[128];
    int tid = threadIdx.x, wid = tid >> 5, lane = tid & 31;
    make_tw(Ef, tid);
    __syncthreads();
    float2* w = ws[wid];
    if (blockIdx.x < 2048){
        int row = blockIdx.x * 8 + wid;       // 0..16383
        int z = row >> 7, y = row & 127;
        float fz = (float)(z - 64) * (1.0f/128.0f);
        float fy = (float)(y - 64) * (1.0f/128.0f);
        float fzy = fz*fz + fy*fy;
        #pragma unroll
        for (int k = 0; k < 4; k++){
            int x = lane + k*32;
            float fx = (float)(x - 64) * (1.0f/128.0f);
            float r  = sqrtf(fzy + fx*fx);
            float wt;
            if (r < 1e-12f) wt = 1.0f;
            else { float pr = 3.14159265358979f * r; wt = __sinf(pr) / pr; }
            wt = wt * wt;
            w[(x + 64) & 127] = make_float2(vol[(z*DN + y)*DN + x] * wt, 0.0f);
        }
        __syncwarp();
        fft128_w32(w, Ef, lane);
        #pragma unroll
        for (int k = 0; k < 3; k++){
            int x = lane + k*32;
            if (x < HK) g_vf[(z*DN + y)*HK + x] = w[x];
        }
    } else {
        int row = (blockIdx.x - 2048) * 8 + wid;  // 0..511
        int b = row >> 7, r = row & 127;
        #pragma unroll
        for (int k = 0; k < 4; k++){
            int x = lane + k*32;
            w[(x + 64) & 127] = make_float2(imgs[(b*DN + r)*DN + x], 0.0f);
        }
        __syncwarp();
        fft128_w32(w, Ef, lane);
        #pragma unroll
        for (int k = 0; k < 3; k++){
            int x = lane + k*32;
            if (x < HK) g_fimg[(b*DN + r)*HK + x] = w[x];
        }
    }
}

// ---------------- pass 2: y-FFT tiles (vol planes + image planes), in place --
__global__ void __launch_bounds__(256) kMid(){
    __shared__ float2 a[8][CP];
    __shared__ float2 Ef[128];
    int tid = threadIdx.x;
    make_tw(Ef, tid);
    float2* base;
    int kt;
    if (blockIdx.x < DN*KT){
        int z = blockIdx.x / KT;
        kt = blockIdx.x % KT;
        base = g_vf + z*DN*HK;
    } else {
        int u = blockIdx.x - DN*KT;
        int b = u / KT;
        kt = u % KT;
        base = g_fimg + b*DN*HK;
    }
    int kx0 = kt * 8;
    #pragma unroll
    for (int k = 0; k < 4; k++){
        int idx = tid + k*256;
        int y = idx >> 3, c = idx & 7;
        int kx = kx0 + c;
        if (kx < HK){
            int ys = (y + 64) & 127;
            a[c][y] = base[ys*HK + kx];
        }
    }
    __syncthreads();
    int wid = tid >> 5, lane = tid & 31;
    if (kx0 + wid < HK) fft128_w32(a[wid], Ef, lane);
    __syncthreads();
    #pragma unroll
    for (int k = 0; k < 4; k++){
        int idx = tid + k*256;
        int y = idx >> 3, c = idx & 7;
        int kx = kx0 + c;
        if (kx < HK){
            int ys = (y + 64) & 127;
            base[ys*HK + kx] = a[c][y];
        }
    }
}

// ---------------- pass 3: z-FFT tiles + x-pair pack; extra blocks build g_fc --
__global__ void __launch_bounds__(256) kVolZT(const float* __restrict__ ctf){
    if (blockIdx.x >= DN*KT){
        int e0 = (blockIdx.x - DN*KT) * 1024 + threadIdx.x * 4;
        #pragma unroll
        for (int k = 0; k < 4; k++){
            int e = e0 + k;
            if (e < BN*DN*HK){
                int l  = e % HK;
                int hb = e / HK;          // b*DN + h
                int h  = hb % DN;
                float sgn = ((h + l) & 1) ? -1.0f : 1.0f;
                if (l != 0 && l != 64) sgn *= 2.0f;
                float cf = __ldg(&ctf[e]) * sgn;
                float2 fi = g_fimg[e];
                g_fc[e] = make_float2(fi.x*cf, fi.y*cf);
            }
        }
        return;
    }
    __shared__ float2 a[8][CP];
    __shared__ float2 Ef[128];
    int tid = threadIdx.x;
    int sy  = blockIdx.x / KT;
    int kt  = blockIdx.x % KT;
    int kx0 = kt * 8;
    make_tw(Ef, tid);
    #pragma unroll
    for (int k = 0; k < 4; k++){
        int idx = tid + k*256;
        int zz = idx >> 3, c = idx & 7;
        int kx = kx0 + c;
        if (kx < HK){
            int zs = (zz + 64) & 127;
            a[c][zz] = g_vf[(zs*DN + sy)*HK + kx];
        }
    }
    __syncthreads();
    int wid = tid >> 5, lane = tid & 31;
    if (kx0 + wid < HK) fft128_w32(a[wid], Ef, lane);
    __syncthreads();
    float2* out2 = (float2*)g_vf4;
    #pragma unroll
    for (int k = 0; k < 4; k++){
        int idx = tid + k*256;
        int zz = idx >> 3, c = idx & 7;
        int kx = kx0 + c;
        if (kx < HK){
            int zs = (zz + 64) & 127;
            float2 V = a[c][zz];
            int base = (zs*DN + sy)*HK + kx;
            out2[2*base] = V;
            if (kx > 0) out2[2*base - 1] = V;
            if (kx == HK-1) out2[2*base + 1] = make_float2(0.f, 0.f);
        }
    }
}

// ---------------- matcher stage A: slice extraction + register iFFT ----------
// one block per (bid, stripe): grid = NBTG*4
__global__ void __launch_bounds__(256) kMatchA(const float* __restrict__ rotm,
                                               const float* __restrict__ gridm){
    __shared__ float2 Pp[32][HK];     // product stripe (signs/alpha folded)
    __shared__ float2 wb[8][128];     // per-warp bitrev scratch
    __shared__ float2 Ei[128];        // exp(+2*pi*i*j/128)
    __shared__ float  Ac[3], Bc[3];

    int tid = threadIdx.x, wid = tid >> 5, lane = tid & 31;
    int bid    = blockIdx.x >> 2;
    int stripe = blockIdx.x & 3;
    int b  = bid / PERB;
    int rr = bid % PERB;
    int t  = rr / GN;
    int g  = rr % GN;
    int hbase = stripe * 32;

    make_twi(Ei, tid);
    if (tid < 3){
        int i  = tid;
        int ii = 2 - i;
        const float* R  = rotm  + ((b*TN + t)*3 + ii)*3;
        const float* Gm = gridm + g*9;
        Ac[i] = R[0]*Gm[1] + R[1]*Gm[4] + R[2]*Gm[7];
        Bc[i] = R[0]*Gm[0] + R[1]*Gm[3] + R[2]*Gm[6];
    }
    __syncthreads();
    float A0=Ac[0], A1=Ac[1], A2=Ac[2], B0=Bc[0], B1=Bc[1], B2=Bc[2];

    // 2-D warp tile shape: minimize predicted (z-lines)x(y-lines) footprint
    int THS;    // log2 of tile height (h direction)
    {
        float a0 = fabsf(A0), a1 = fabsf(A1);
        float b0 = fabsf(B0), b1 = fabsf(B1);
        float m48 = (4.f*a0 + 8.f*b0 + 1.f) * (4.f*a1 + 8.f*b1 + 1.f);  // 4h x 8l
        float m84 = (8.f*a0 + 4.f*b0 + 1.f) * (8.f*a1 + 4.f*b1 + 1.f);  // 8h x 4l
        THS = (m48 <= m84) ? 2 : 3;
    }
    int TH  = 1 << THS;          // 4 or 8
    int TL  = 32 >> THS;         // 8 or 4
    int nht = 32 >> THS;         // 8 or 4 h-tiles
    int nlt = (HK + TL - 1) / TL;
    int nt  = nht * nlt;         // 72 or 68 tiles

    float2 T1a = Ei[lane];
    float2 T1b = Ei[lane + 32];
    float2 T2  = Ei[2*lane];
    float2 T3  = Ei[(lane & 15)*4];
    float2 T4  = Ei[(lane & 7)*8];
    float2 T5  = Ei[(lane & 3)*16];
    float2 T6  = Ei[(lane & 1)*32];

    const float2* fcb = g_fc + b*DN*HK;

    // ---- stage 0: slice extraction + product, warp = TH x TL point tile ----
    for (int tix = wid; tix < nt; tix += 8){
        int ht = tix / nlt, lt = tix - ht*nlt;
        int hh = ht*TH + (lane & (TH - 1));
        int l  = lt*TL + (lane >> THS);
        if (l < HK){
            int h  = hbase + hh;
            float hm = (float)(h - 64);
            float lf = (float)l;
            float v0 = A0*hm + B0*lf;
            float v1 = A1*hm + B1*lf;
            float v2 = A2*hm + B2*lf;
            bool neg = (v2 < 0.0f);
            if (neg){ v0 = -v0; v1 = -v1; v2 = -v2; }
            float zc = v0 + 64.0f, yc = v1 + 64.0f, xc = v2;
            float zf = floorf(zc), yf = floorf(yc), xf = floorf(xc);
            int z0 = (int)zf, y0 = (int)yf, x0 = (int)xf;
            float fz = zc - zf, fy = yc - yf, fx = xc - xf;
            float2 acc = make_float2(0.0f, 0.0f);
            if (x0 < HK){                      // x0 >= 0 guaranteed (xc >= 0)
                float fx1 = 1.0f - fx;
                #pragma unroll
                for (int dz = 0; dz < 2; dz++){
                    int zi = z0 + dz;
                    if (zi < 0 || zi >= DN) continue;
                    float wz = dz ? fz : 1.0f - fz;
                    #pragma unroll
                    for (int dy = 0; dy < 2; dy++){
                        int yi = y0 + dy;
                        if (yi < 0 || yi >= DN) continue;
                        float wzy = wz * (dy ? fy : 1.0f - fy);
                        float4 q = __ldg(&g_vf4[(zi*DN + yi)*HK + x0]);
                        acc.x += wzy * (fx1*q.x + fx*q.z);
                        acc.y += wzy * (fx1*q.y + fx*q.w);
                    }
                }
            }
            if (neg) acc.y = -acc.y;             // conj
            float2 fi = __ldg(&fcb[h*HK + l]);   // ctf*fimg*sign*alpha prefolded
            Pp[hh][l] = make_float2(fi.x*acc.x + fi.y*acc.y,
                                    fi.y*acc.x - fi.x*acc.y);
        }
    }
    __syncthreads();

    // ---- stage 1: zero-padded 128-pt register inverse FFT per row -----------
    {
        float2* col = wb[wid];
        #pragma unroll
        for (int rr2 = 0; rr2 < 4; rr2++){
            int row = 4*wid + rr2;
            float2 r0 = Pp[row][lane];
            float2 r1 = Pp[row][lane + 32];
            float2 r2 = (lane == 0) ? Pp[row][64] : make_float2(0.f, 0.f);
            float2 r3;
            { float2 d = csub(r0, r2); r0 = cadd(r0, r2); r2 = cmulf(d, T1a);
              r3 = cmulf(r1, T1b); }
            { float2 d = csub(r0, r1); r0 = cadd(r0, r1); r1 = cmulf(d, T2);
              float2 e = csub(r2, r3); r2 = cadd(r2, r3); r3 = cmulf(e, T2); }
            bfx(r0, 16, T3, lane); bfx(r1, 16, T3, lane); bfx(r2, 16, T3, lane); bfx(r3, 16, T3, lane);
            bfx(r0,  8, T4, lane); bfx(r1,  8, T4, lane); bfx(r2,  8, T4, lane); bfx(r3,  8, T4, lane);
            bfx(r0,  4, T5, lane); bfx(r1,  4, T5, lane); bfx(r2,  4, T5, lane); bfx(r3,  4, T5, lane);
            bfx(r0,  2, T6, lane); bfx(r1,  2, T6, lane); bfx(r2,  2, T6, lane); bfx(r3,  2, T6, lane);
            bf1(r0, lane); bf1(r1, lane); bf1(r2, lane); bf1(r3, lane);
            col[rev7(lane      )] = r0;
            col[rev7(lane + 32 )] = r1;
            col[rev7(lane + 64 )] = r2;
            col[rev7(lane + 96 )] = r3;
            __syncwarp();
            if (lane < WIN)
                g_G1[(bid*DN + hbase + row)*WIN + lane] = col[H0 + lane];
            __syncwarp();
        }
    }
}

// ---------------- matcher stage B: register iFFT per column + argmax ---------
__global__ void __launch_bounds__(256) kMatchB(){
    __shared__ float2 G1s[DN][WIN+1];
    __shared__ float  wbf[8][128];
    __shared__ float2 Ei[128];
    __shared__ float  rv[256];
    __shared__ int    ri[256];
    int tid = threadIdx.x, wid = tid >> 5, lane = tid & 31;
    int bid = blockIdx.x;

    make_twi(Ei, tid);
    const float2* src = g_G1 + bid*DN*WIN;
    for (int idx = tid; idx < DN*WIN; idx += 256)
        G1s[idx / WIN][idx % WIN] = src[idx];
    __syncthreads();

    float2 T1a = Ei[lane];
    float2 T1b = Ei[lane + 32];
    float2 T2  = Ei[2*lane];
    float2 T3  = Ei[(lane & 15)*4];
    float2 T4  = Ei[(lane & 7)*8];
    float2 T5  = Ei[(lane & 3)*16];
    float2 T6  = Ei[(lane & 1)*32];

    float best = -3.4e38f;
    int bestIdx = 0x7fffffff;
    {
        float* colf = wbf[wid];
        #pragma unroll
        for (int j = 0; j < 3; j++){
            int v = 3*wid + j;
            float2 r0 = G1s[lane      ][v];
            float2 r1 = G1s[lane + 32 ][v];
            float2 r2 = G1s[lane + 64 ][v];
            float2 r3 = G1s[lane + 96 ][v];
            { float2 d = csub(r0, r2); r0 = cadd(r0, r2); r2 = cmulf(d, T1a);
              float2 e = csub(r1, r3); r1 = cadd(r1, r3); r3 = cmulf(e, T1b); }
            { float2 d = csub(r0, r1); r0 = cadd(r0, r1); r1 = cmulf(d, T2);
              float2 e = csub(r2, r3); r2 = cadd(r2, r3); r3 = cmulf(e, T2); }
            bfx(r0, 16, T3, lane); bfx(r1, 16, T3, lane); bfx(r2, 16, T3, lane); bfx(r3, 16, T3, lane);
            bfx(r0,  8, T4, lane); bfx(r1,  8, T4, lane); bfx(r2,  8, T4, lane); bfx(r3,  8, T4, lane);
            bfx(r0,  4, T5, lane); bfx(r1,  4, T5, lane); bfx(r2,  4, T5, lane); bfx(r3,  4, T5, lane);
            bfx(r0,  2, T6, lane); bfx(r1,  2, T6, lane); bfx(r2,  2, T6, lane); bfx(r3,  2, T6, lane);
            bf1(r0, lane); bf1(r1, lane); bf1(r2, lane); bf1(r3, lane);
            colf[rev7(lane      )] = r0.x;
            colf[rev7(lane + 32 )] = r1.x;
            colf[rev7(lane + 64 )] = r2.x;
            colf[rev7(lane + 96 )] = r3.x;
            __syncwarp();
            if (lane < WIN){
                int u = lane;
                float val = colf[H0 + u] * (1.0f/16384.0f);
                if (u & 1) val = -val;               // (-1)^(52+u)
                int idx = u*WIN + v;
                if (val > best || (val == best && idx < bestIdx)){ best = val; bestIdx = idx; }
            }
            __syncwarp();
        }
    }
    rv[tid] = best; ri[tid] = bestIdx;
    __syncthreads();
    for (int s = 128; s; s >>= 1){
        if (tid < s){
            float v2 = rv[tid+s]; int i2 = ri[tid+s];
            if (v2 > rv[tid] || (v2 == rv[tid] && i2 < ri[tid])){ rv[tid] = v2; ri[tid] = i2; }
        }
        __syncthreads();
    }
    if (tid == 0){ g_corr[bid] = rv[0]; g_argm[bid] = ri[0]; }
}

// ---------------- final per-batch reduction ----------------
__global__ void __launch_bounds__(256) kReduce(const float* __restrict__ gridm,
                                               float* __restrict__ out){
    __shared__ float sv[256];
    __shared__ int   si[256];
    __shared__ float s_mean, s_std;
    __shared__ float s_val[2];
    __shared__ int   s_idx[2];
    int b = blockIdx.x, tid = threadIdx.x;
    float v = (tid < PERB) ? g_corr[b*PERB + tid] : 0.0f;

    sv[tid] = (tid < PERB) ? v : 0.0f;
    __syncthreads();
    for (int s = 128; s; s >>= 1){ if (tid < s) sv[tid] += sv[tid+s]; __syncthreads(); }
    if (tid == 0) s_mean = sv[0] / (float)PERB;
    __syncthreads();
    float mean = s_mean;
    float d = (tid < PERB) ? (v - mean) : 0.0f;
    sv[tid] = d * d;
    __syncthreads();
    for (int s = 128; s; s >>= 1){ if (tid < s) sv[tid] += sv[tid+s]; __syncthreads(); }
    if (tid == 0) s_std = sqrtf(sv[0] / (float)(PERB - 1));
    __syncthreads();
    float stdv = s_std;

    for (int k = 0; k < 2; k++){
        bool excl = (k == 1 && tid == s_idx[0]);
        sv[tid] = (tid < PERB && !excl) ? v : -3.4e38f;
        si[tid] = tid;
        __syncthreads();
        for (int s = 128; s; s >>= 1){
            if (tid < s){
                float v2 = sv[tid+s]; int i2 = si[tid+s];
                if (v2 > sv[tid] || (v2 == sv[tid] && i2 < si[tid])){ sv[tid] = v2; si[tid] = i2; }
            }
            __syncthreads();
        }
        if (tid == 0){ s_val[k] = sv[0]; s_idx[k] = si[0]; }
        __syncthreads();
    }

    if (tid < 2){
        int k = tid;
        float val = s_val[k];
        int   idx = s_idx[k];
        int   gg  = idx % GN;
        int   a   = g_argm[b*PERB + idx];
        int   u   = a / WIN;
        int   vv  = a - u*WIN;
        int slot  = b*2 + k;
        out[slot] = val;
        for (int j = 0; j < 9; j++) out[8 + slot*9 + j] = gridm[gg*9 + j];
        out[80 + slot*2 + 0] = -((float)(H0 + vv) - 64.0f) * 1.5f;
        out[80 + slot*2 + 1] = -((float)(H0 + u)  - 64.0f) * 1.5f;
        float zz = (val - mean) / (stdv * 1.41421356237f);
        out[96 + slot] = 0.5f * (1.0f + erff(zz));
    }
}

// ---------------- launch ----------------
extern "C" void kernel_launch(void* const* d_in, const int* in_sizes, int n_in,
                              void* d_out, int out_size){
    const float* vol   = (const float*)d_in[0];
    const float* imgs  = (const float*)d_in[1];
    const float* ctf   = (const float*)d_in[2];
    const float* rotm  = (const float*)d_in[3];
    const float* gridm = (const float*)d_in[4];

    kPre<<<2112, 256>>>(vol, imgs);              // launch 1: vol-X + img rows
    kMid<<<DN*KT + BN*KT, 256>>>();              // launch 2: vol-Y + img cols
    kVolZT<<<DN*KT + FCB, 256>>>(ctf);           // launch 3: vol-Z + pack + fc
    kMatchA<<<NBTG*4, 256>>>(rotm, gridm);       // launch 4  <- profiled
    kMatchB<<<NBTG, 256>>>();                    // launch 5
    kReduce<<<BN, 256>>>(gridm, (float*)d_out);  // launch 6
}

// round 15
// speedup vs baseline: 1.0822x; 1.0822x over previous
#include <cuda_runtime.h>
#include <cuda_fp16.h>
#include <math.h>

#define DN   128
#define HK   65
#define BN   4
#define TN   2
#define GN   125
#define PERB (TN*GN)      // 250
#define NBTG (BN*PERB)    // 1000
#define WIN  24
#define H0   52
#define KT   9            // ceil(65/8) kx tiles
#define CP   130          // padded column stride for tile kernels
#define FCB  33           // blocks for fc premultiply: ceil(4*128*65/1024)

// ---------------- scratch (static device memory; no allocation) ----------------
__device__ float2 g_vf[DN*DN*HK];       // vol rfft (float, built by 3 FFT passes)
__device__ uint4  g_vq[DN*DN*HK];       // fp16 corner-quad volume (17 MB)
__device__ float2 g_fimg[BN*DN*HK];     // image rffts, y fftshifted
__device__ float2 g_fc[BN*DN*HK];       // ctf*fimg*sign*alpha, precombined
__device__ float2 g_G1[NBTG*DN*WIN];    // stage-1 results (24.6 MB)
__device__ float  g_corr[NBTG];
__device__ int    g_argm[NBTG];

__device__ __forceinline__ float2 cmulf(float2 a, float2 b){
    return make_float2(a.x*b.x - a.y*b.y, a.x*b.y + a.y*b.x);
}
__device__ __forceinline__ float2 cadd(float2 a, float2 b){ return make_float2(a.x+b.x, a.y+b.y); }
__device__ __forceinline__ float2 csub(float2 a, float2 b){ return make_float2(a.x-b.x, a.y-b.y); }
__device__ __forceinline__ int rev7(int p){ return (int)(__brev((unsigned)p) >> 25); }

__device__ __forceinline__ unsigned int f2h2(float2 v){
    __half2 h = __floats2half2_rn(v.x, v.y);
    return *reinterpret_cast<unsigned int*>(&h);
}
__device__ __forceinline__ float2 h2f2(unsigned int u){
    __half2 h = *reinterpret_cast<__half2*>(&u);
    return __half22float2(h);
}

__device__ __forceinline__ void make_tw(float2* Ef, int tid){
    if (tid < 128){
        float s, c;
        sincosf(-6.283185307179586f * (float)tid * (1.0f/128.0f), &s, &c);
        Ef[tid] = make_float2(c, s);
    }
}
__device__ __forceinline__ void make_twi(float2* Ei, int tid){
    if (tid < 128){
        float s, c;
        sincosf(6.283185307179586f * (float)tid * (1.0f/128.0f), &s, &c);
        Ei[tid] = make_float2(c, s);
    }
}

// shfl-xor DIF butterfly
__device__ __forceinline__ void bfx(float2& r, int mask, float2 tw, int lane){
    float ox = __shfl_xor_sync(0xffffffffu, r.x, mask);
    float oy = __shfl_xor_sync(0xffffffffu, r.y, mask);
    if ((lane & mask) == 0){ r.x += ox; r.y += oy; }
    else { float ux = ox - r.x, uy = oy - r.y; r = make_float2(ux*tw.x - uy*tw.y, ux*tw.y + uy*tw.x); }
}
__device__ __forceinline__ void bf1(float2& r, int lane){
    float ox = __shfl_xor_sync(0xffffffffu, r.x, 1);
    float oy = __shfl_xor_sync(0xffffffffu, r.y, 1);
    if ((lane & 1) == 0){ r.x += ox; r.y += oy; }
    else { r.x = ox - r.x; r.y = oy - r.y; }
}

// ---------------- warp-local smem 128-pt FFT (volume/image passes) -----------
__device__ __forceinline__ void fft128_w32(float2* col, const float2* Ef, int lane){
    for (int shift = 6; shift >= 0; shift--){
        int half = 1 << shift;
        int twsh = 6 - shift;
        #pragma unroll
        for (int k = 0; k < 2; k++){
            int bf   = lane + k*32;
            int j    = bf & (half - 1);
            int grp  = bf >> shift;
            int base = (grp << (shift + 1)) + j;
            float2 u = col[base];
            float2 v = col[base + half];
            float2 d = make_float2(u.x - v.x, u.y - v.y);
            col[base]        = make_float2(u.x + v.x, u.y + v.y);
            col[base + half] = cmulf(d, Ef[j << twsh]);
        }
        __syncwarp();
    }
    float2 r[4];
    #pragma unroll
    for (int k = 0; k < 4; k++) r[k] = col[lane + k*32];
    __syncwarp();
    #pragma unroll
    for (int k = 0; k < 4; k++){
        int y = lane + k*32;
        col[rev7(y)] = r[k];
    }
    __syncwarp();
}

// ---------------- pass 1: row rffts (vol rows + img rows), warp-per-row ------
__global__ void __launch_bounds__(256) kPre(const float* __restrict__ vol,
                                            const float* __restrict__ imgs){
    __shared__ float2 ws[8][128];
    __shared__ float2 Ef[128];
    int tid = threadIdx.x, wid = tid >> 5, lane = tid & 31;
    make_tw(Ef, tid);
    __syncthreads();
    float2* w = ws[wid];
    if (blockIdx.x < 2048){
        int row = blockIdx.x * 8 + wid;       // 0..16383
        int z = row >> 7, y = row & 127;
        float fz = (float)(z - 64) * (1.0f/128.0f);
        float fy = (float)(y - 64) * (1.0f/128.0f);
        float fzy = fz*fz + fy*fy;
        #pragma unroll
        for (int k = 0; k < 4; k++){
            int x = lane + k*32;
            float fx = (float)(x - 64) * (1.0f/128.0f);
            float r  = sqrtf(fzy + fx*fx);
            float wt;
            if (r < 1e-12f) wt = 1.0f;
            else { float pr = 3.14159265358979f * r; wt = __sinf(pr) / pr; }
            wt = wt * wt;
            w[(x + 64) & 127] = make_float2(vol[(z*DN + y)*DN + x] * wt, 0.0f);
        }
        __syncwarp();
        fft128_w32(w, Ef, lane);
        #pragma unroll
        for (int k = 0; k < 3; k++){
            int x = lane + k*32;
            if (x < HK) g_vf[(z*DN + y)*HK + x] = w[x];
        }
    } else {
        int row = (blockIdx.x - 2048) * 8 + wid;  // 0..511
        int b = row >> 7, r = row & 127;
        #pragma unroll
        for (int k = 0; k < 4; k++){
            int x = lane + k*32;
            w[(x + 64) & 127] = make_float2(imgs[(b*DN + r)*DN + x], 0.0f);
        }
        __syncwarp();
        fft128_w32(w, Ef, lane);
        #pragma unroll
        for (int k = 0; k < 3; k++){
            int x = lane + k*32;
            if (x < HK) g_fimg[(b*DN + r)*HK + x] = w[x];
        }
    }
}

// ---------------- pass 2: y-FFT tiles (vol planes + image planes), in place --
__global__ void __launch_bounds__(256) kMid(){
    __shared__ float2 a[8][CP];
    __shared__ float2 Ef[128];
    int tid = threadIdx.x;
    make_tw(Ef, tid);
    float2* base;
    int kt;
    if (blockIdx.x < DN*KT){
        int z = blockIdx.x / KT;
        kt = blockIdx.x % KT;
        base = g_vf + z*DN*HK;
    } else {
        int u = blockIdx.x - DN*KT;
        int b = u / KT;
        kt = u % KT;
        base = g_fimg + b*DN*HK;
    }
    int kx0 = kt * 8;
    #pragma unroll
    for (int k = 0; k < 4; k++){
        int idx = tid + k*256;
        int y = idx >> 3, c = idx & 7;
        int kx = kx0 + c;
        if (kx < HK){
            int ys = (y + 64) & 127;
            a[c][y] = base[ys*HK + kx];
        }
    }
    __syncthreads();
    int wid = tid >> 5, lane = tid & 31;
    if (kx0 + wid < HK) fft128_w32(a[wid], Ef, lane);
    __syncthreads();
    #pragma unroll
    for (int k = 0; k < 4; k++){
        int idx = tid + k*256;
        int y = idx >> 3, c = idx & 7;
        int kx = kx0 + c;
        if (kx < HK){
            int ys = (y + 64) & 127;
            base[ys*HK + kx] = a[c][y];
        }
    }
}

// ---------------- pass 3: z-FFT tiles on volume, in place --------------------
__global__ void __launch_bounds__(256) kVolZT(){
    __shared__ float2 a[8][CP];
    __shared__ float2 Ef[128];
    int tid = threadIdx.x;
    int sy  = blockIdx.x / KT;
    int kt  = blockIdx.x % KT;
    int kx0 = kt * 8;
    make_tw(Ef, tid);
    #pragma unroll
    for (int k = 0; k < 4; k++){
        int idx = tid + k*256;
        int zz = idx >> 3, c = idx & 7;
        int kx = kx0 + c;
        if (kx < HK){
            int zs = (zz + 64) & 127;
            a[c][zz] = g_vf[(zs*DN + sy)*HK + kx];
        }
    }
    __syncthreads();
    int wid = tid >> 5, lane = tid & 31;
    if (kx0 + wid < HK) fft128_w32(a[wid], Ef, lane);
    __syncthreads();
    #pragma unroll
    for (int k = 0; k < 4; k++){
        int idx = tid + k*256;
        int zz = idx >> 3, c = idx & 7;
        int kx = kx0 + c;
        if (kx < HK){
            int zs = (zz + 64) & 127;
            g_vf[(zs*DN + sy)*HK + kx] = a[c][zz];
        }
    }
}

// ---------------- pass 4: build fp16 corner-quad volume + fc premultiply -----
// blocks [0,DN): plane z quad pack; blocks [DN, DN+FCB): fc premultiply.
__global__ void __launch_bounds__(256) kPack(const float* __restrict__ ctf){
    if (blockIdx.x >= DN){
        int e0 = (blockIdx.x - DN) * 1024 + threadIdx.x * 4;
        #pragma unroll
        for (int k = 0; k < 4; k++){
            int e = e0 + k;
            if (e < BN*DN*HK){
                int l  = e % HK;
                int hb = e / HK;          // b*DN + h
                int h  = hb % DN;
                float sgn = ((h + l) & 1) ? -1.0f : 1.0f;
                if (l != 0 && l != 64) sgn *= 2.0f;
                float cf = __ldg(&ctf[e]) * sgn;
                float2 fi = g_fimg[e];
                g_fc[e] = make_float2(fi.x*cf, fi.y*cf);
            }
        }
        return;
    }
    int z = blockIdx.x;
    const float2* pl  = g_vf + z*DN*HK;
    for (int idx = threadIdx.x; idx < DN*HK; idx += 256){
        int y = idx / HK;
        int x = idx - y*HK;
        float2 zero = make_float2(0.f, 0.f);
        float2 v00 = pl[y*HK + x];
        float2 v01 = (x+1 < HK) ? pl[y*HK + x + 1] : zero;
        float2 v10 = (y+1 < DN) ? pl[(y+1)*HK + x] : zero;
        float2 v11 = (y+1 < DN && x+1 < HK) ? pl[(y+1)*HK + x + 1] : zero;
        g_vq[(z*DN + y)*HK + x] = make_uint4(f2h2(v00), f2h2(v01), f2h2(v10), f2h2(v11));
    }
}

// ---------------- matcher stage A: quad gather + register iFFT ---------------
// one block per (bid, stripe): grid = NBTG*4
__global__ void __launch_bounds__(256) kMatchA(const float* __restrict__ rotm,
                                               const float* __restrict__ gridm){
    __shared__ float2 Pp[32][HK];     // product stripe
    __shared__ float2 wb[8][128];     // per-warp bitrev scratch
    __shared__ float2 Ei[128];        // exp(+2*pi*i*j/128)
    __shared__ float  Ac[3], Bc[3];

    int tid = threadIdx.x, wid = tid >> 5, lane = tid & 31;
    int bid    = blockIdx.x >> 2;
    int stripe = blockIdx.x & 3;
    int b  = bid / PERB;
    int rr = bid % PERB;
    int t  = rr / GN;
    int g  = rr % GN;
    int hbase = stripe * 32;

    make_twi(Ei, tid);
    if (tid < 3){
        int i  = tid;
        int ii = 2 - i;
        const float* R  = rotm  + ((b*TN + t)*3 + ii)*3;
        const float* Gm = gridm + g*9;
        Ac[i] = R[0]*Gm[1] + R[1]*Gm[4] + R[2]*Gm[7];
        Bc[i] = R[0]*Gm[0] + R[1]*Gm[3] + R[2]*Gm[6];
    }
    __syncthreads();
    float A0=Ac[0], A1=Ac[1], A2=Ac[2], B0=Bc[0], B1=Bc[1], B2=Bc[2];
    bool stepH = fabsf(A2) > fabsf(B2);   // lanes step along fastest-x direction

    float2 T1a = Ei[lane];
    float2 T1b = Ei[lane + 32];
    float2 T2  = Ei[2*lane];
    float2 T3  = Ei[(lane & 15)*4];
    float2 T4  = Ei[(lane & 7)*8];
    float2 T5  = Ei[(lane & 3)*16];
    float2 T6  = Ei[(lane & 1)*32];

    const float2* fcb = g_fc + b*DN*HK;

    // ---- stage 0: slice extraction (2x16B quad loads per point) + product ----
    for (int idx = tid; idx < 32*HK; idx += 256){
        int hh, l;
        if (stepH){ l = idx >> 5; hh = idx & 31; }
        else      { hh = idx / HK; l = idx - hh*HK; }
        int h  = hbase + hh;
        float hm = (float)(h - 64);
        float lf = (float)l;
        float v0 = A0*hm + B0*lf;
        float v1 = A1*hm + B1*lf;
        float v2 = A2*hm + B2*lf;
        bool neg = (v2 < 0.0f);
        if (neg){ v0 = -v0; v1 = -v1; v2 = -v2; }
        float zc = v0 + 64.0f, yc = v1 + 64.0f, xc = v2;
        float zf = floorf(zc), yf = floorf(yc), xf = floorf(xc);
        int z0 = (int)zf, y0 = (int)yf, x0 = (int)xf;
        float fz = zc - zf, fy = yc - yf, fx = xc - xf;
        float2 acc = make_float2(0.0f, 0.0f);
        if (x0 < HK && z0 >= -1 && z0 < DN && y0 >= -1 && y0 < DN){
            float fx1 = 1.0f - fx;
            int   za  = (z0 >= 0)     ? z0     : 0;
            float wz0 = (z0 >= 0)     ? 1.0f - fz : 0.0f;
            int   zb  = (z0+1 < DN)   ? z0+1   : 0;
            float wz1 = (z0+1 < DN)   ? fz     : 0.0f;
            int   yq;  float wyA, wyB;
            if (y0 >= 0){ yq = y0; wyA = 1.0f - fy; wyB = fy; }
            else        { yq = 0;  wyA = fy;        wyB = 0.0f; }
            uint4 qA = __ldg(&g_vq[(za*DN + yq)*HK + x0]);
            uint4 qB = __ldg(&g_vq[(zb*DN + yq)*HK + x0]);
            float wA0 = wz0*wyA*fx1, wA1 = wz0*wyA*fx;
            float wA2 = wz0*wyB*fx1, wA3 = wz0*wyB*fx;
            float wB0 = wz1*wyA*fx1, wB1 = wz1*wyA*fx;
            float wB2 = wz1*wyB*fx1, wB3 = wz1*wyB*fx;
            float2 a00 = h2f2(qA.x), a01 = h2f2(qA.y), a10 = h2f2(qA.z), a11 = h2f2(qA.w);
            float2 b00 = h2f2(qB.x), b01 = h2f2(qB.y), b10 = h2f2(qB.z), b11 = h2f2(qB.w);
            acc.x = wA0*a00.x + wA1*a01.x + wA2*a10.x + wA3*a11.x
                  + wB0*b00.x + wB1*b01.x + wB2*b10.x + wB3*b11.x;
            acc.y = wA0*a00.y + wA1*a01.y + wA2*a10.y + wA3*a11.y
                  + wB0*b00.y + wB1*b01.y + wB2*b10.y + wB3*b11.y;
        }
        if (neg) acc.y = -acc.y;                 // conj
        float2 fi = __ldg(&fcb[h*HK + l]);       // ctf*fimg*sign*alpha prefolded
        Pp[hh][l] = make_float2(fi.x*acc.x + fi.y*acc.y,
                                fi.y*acc.x - fi.x*acc.y);
    }
    __syncthreads();

    // ---- stage 1: zero-padded 128-pt register inverse FFT per row -----------
    {
        float2* col = wb[wid];
        #pragma unroll
        for (int rr2 = 0; rr2 < 4; rr2++){
            int row = 4*wid + rr2;
            float2 r0 = Pp[row][lane];
            float2 r1 = Pp[row][lane + 32];
            float2 r2 = (lane == 0) ? Pp[row][64] : make_float2(0.f, 0.f);
            float2 r3;
            { float2 d = csub(r0, r2); r0 = cadd(r0, r2); r2 = cmulf(d, T1a);
              r3 = cmulf(r1, T1b); }
            { float2 d = csub(r0, r1); r0 = cadd(r0, r1); r1 = cmulf(d, T2);
              float2 e = csub(r2, r3); r2 = cadd(r2, r3); r3 = cmulf(e, T2); }
            bfx(r0, 16, T3, lane); bfx(r1, 16, T3, lane); bfx(r2, 16, T3, lane); bfx(r3, 16, T3, lane);
            bfx(r0,  8, T4, lane); bfx(r1,  8, T4, lane); bfx(r2,  8, T4, lane); bfx(r3,  8, T4, lane);
            bfx(r0,  4, T5, lane); bfx(r1,  4, T5, lane); bfx(r2,  4, T5, lane); bfx(r3,  4, T5, lane);
            bfx(r0,  2, T6, lane); bfx(r1,  2, T6, lane); bfx(r2,  2, T6, lane); bfx(r3,  2, T6, lane);
            bf1(r0, lane); bf1(r1, lane); bf1(r2, lane); bf1(r3, lane);
            col[rev7(lane      )] = r0;
            col[rev7(lane + 32 )] = r1;
            col[rev7(lane + 64 )] = r2;
            col[rev7(lane + 96 )] = r3;
            __syncwarp();
            if (lane < WIN)
                g_G1[(bid*DN + hbase + row)*WIN + lane] = col[H0 + lane];
            __syncwarp();
        }
    }
}

// ---------------- matcher stage B: register iFFT per column + argmax ---------
__global__ void __launch_bounds__(256) kMatchB(){
    __shared__ float2 G1s[DN][WIN+1];
    __shared__ float  wbf[8][128];
    __shared__ float2 Ei[128];
    __shared__ float  rv[256];
    __shared__ int    ri[256];
    int tid = threadIdx.x, wid = tid >> 5, lane = tid & 31;
    int bid = blockIdx.x;

    make_twi(Ei, tid);
    const float2* src = g_G1 + bid*DN*WIN;
    for (int idx = tid; idx < DN*WIN; idx += 256)
        G1s[idx / WIN][idx % WIN] = src[idx];
    __syncthreads();

    float2 T1a = Ei[lane];
    float2 T1b = Ei[lane + 32];
    float2 T2  = Ei[2*lane];
    float2 T3  = Ei[(lane & 15)*4];
    float2 T4  = Ei[(lane & 7)*8];
    float2 T5  = Ei[(lane & 3)*16];
    float2 T6  = Ei[(lane & 1)*32];

    float best = -3.4e38f;
    int bestIdx = 0x7fffffff;
    {
        float* colf = wbf[wid];
        #pragma unroll
        for (int j = 0; j < 3; j++){
            int v = 3*wid + j;
            float2 r0 = G1s[lane      ][v];
            float2 r1 = G1s[lane + 32 ][v];
            float2 r2 = G1s[lane + 64 ][v];
            float2 r3 = G1s[lane + 96 ][v];
            { float2 d = csub(r0, r2); r0 = cadd(r0, r2); r2 = cmulf(d, T1a);
              float2 e = csub(r1, r3); r1 = cadd(r1, r3); r3 = cmulf(e, T1b); }
            { float2 d = csub(r0, r1); r0 = cadd(r0, r1); r1 = cmulf(d, T2);
              float2 e = csub(r2, r3); r2 = cadd(r2, r3); r3 = cmulf(e, T2); }
            bfx(r0, 16, T3, lane); bfx(r1, 16, T3, lane); bfx(r2, 16, T3, lane); bfx(r3, 16, T3, lane);
            bfx(r0,  8, T4, lane); bfx(r1,  8, T4, lane); bfx(r2,  8, T4, lane); bfx(r3,  8, T4, lane);
            bfx(r0,  4, T5, lane); bfx(r1,  4, T5, lane); bfx(r2,  4, T5, lane); bfx(r3,  4, T5, lane);
            bfx(r0,  2, T6, lane); bfx(r1,  2, T6, lane); bfx(r2,  2, T6, lane); bfx(r3,  2, T6, lane);
            bf1(r0, lane); bf1(r1, lane); bf1(r2, lane); bf1(r3, lane);
            colf[rev7(lane      )] = r0.x;
            colf[rev7(lane + 32 )] = r1.x;
            colf[rev7(lane + 64 )] = r2.x;
            colf[rev7(lane + 96 )] = r3.x;
            __syncwarp();
            if (lane < WIN){
                int u = lane;
                float val = colf[H0 + u] * (1.0f/16384.0f);
                if (u & 1) val = -val;               // (-1)^(52+u)
                int idx = u*WIN + v;
                if (val > best || (val == best && idx < bestIdx)){ best = val; bestIdx = idx; }
            }
            __syncwarp();
        }
    }
    rv[tid] = best; ri[tid] = bestIdx;
    __syncthreads();
    for (int s = 128; s; s >>= 1){
        if (tid < s){
            float v2 = rv[tid+s]; int i2 = ri[tid+s];
            if (v2 > rv[tid] || (v2 == rv[tid] && i2 < ri[tid])){ rv[tid] = v2; ri[tid] = i2; }
        }
        __syncthreads();
    }
    if (tid == 0){ g_corr[bid] = rv[0]; g_argm[bid] = ri[0]; }
}

// ---------------- final per-batch reduction ----------------
__global__ void __launch_bounds__(256) kReduce(const float* __restrict__ gridm,
                                               float* __restrict__ out){
    __shared__ float sv[256];
    __shared__ int   si[256];
    __shared__ float s_mean, s_std;
    __shared__ float s_val[2];
    __shared__ int   s_idx[2];
    int b = blockIdx.x, tid = threadIdx.x;
    float v = (tid < PERB) ? g_corr[b*PERB + tid] : 0.0f;

    sv[tid] = (tid < PERB) ? v : 0.0f;
    __syncthreads();
    for (int s = 128; s; s >>= 1){ if (tid < s) sv[tid] += sv[tid+s]; __syncthreads(); }
    if (tid == 0) s_mean = sv[0] / (float)PERB;
    __syncthreads();
    float mean = s_mean;
    float d = (tid < PERB) ? (v - mean) : 0.0f;
    sv[tid] = d * d;
    __syncthreads();
    for (int s = 128; s; s >>= 1){ if (tid < s) sv[tid] += sv[tid+s]; __syncthreads(); }
    if (tid == 0) s_std = sqrtf(sv[0] / (float)(PERB - 1));
    __syncthreads();
    float stdv = s_std;

    for (int k = 0; k < 2; k++){
        bool excl = (k == 1 && tid == s_idx[0]);
        sv[tid] = (tid < PERB && !excl) ? v : -3.4e38f;
        si[tid] = tid;
        __syncthreads();
        for (int s = 128; s; s >>= 1){
            if (tid < s){
                float v2 = sv[tid+s]; int i2 = si[tid+s];
                if (v2 > sv[tid] || (v2 == sv[tid] && i2 < si[tid])){ sv[tid] = v2; si[tid] = i2; }
            }
            __syncthreads();
        }
        if (tid == 0){ s_val[k] = sv[0]; s_idx[k] = si[0]; }
        __syncthreads();
    }

    if (tid < 2){
        int k = tid;
        float val = s_val[k];
        int   idx = s_idx[k];
        int   gg  = idx % GN;
        int   a   = g_argm[b*PERB + idx];
        int   u   = a / WIN;
        int   vv  = a - u*WIN;
        int slot  = b*2 + k;
        out[slot] = val;
        for (int j = 0; j < 9; j++) out[8 + slot*9 + j] = gridm[gg*9 + j];
        out[80 + slot*2 + 0] = -((float)(H0 + vv) - 64.0f) * 1.5f;
        out[80 + slot*2 + 1] = -((float)(H0 + u)  - 64.0f) * 1.5f;
        float zz = (val - mean) / (stdv * 1.41421356237f);
        out[96 + slot] = 0.5f * (1.0f + erff(zz));
    }
}

// ---------------- launch ----------------
extern "C" void kernel_launch(void* const* d_in, const int* in_sizes, int n_in,
                              void* d_out, int out_size){
    const float* vol   = (const float*)d_in[0];
    const float* imgs  = (const float*)d_in[1];
    const float* ctf   = (const float*)d_in[2];
    const float* rotm  = (const float*)d_in[3];
    const float* gridm = (const float*)d_in[4];

    kPre<<<2112, 256>>>(vol, imgs);              // launch 1: vol-X + img rows
    kMid<<<DN*KT + BN*KT, 256>>>();              // launch 2: vol-Y + img cols
    kVolZT<<<DN*KT, 256>>>();                    // launch 3: vol-Z in place
    kPack<<<DN + FCB, 256>>>(ctf);               // launch 4: fp16 quads + fc
    kMatchA<<<NBTG*4, 256>>>(rotm, gridm);       // launch 5
    kMatchB<<<NBTG, 256>>>();                    // launch 6
    kReduce<<<BN, 256>>>(gridm, (float*)d_out);  // launch 7
}

// round 16
// speedup vs baseline: 1.1322x; 1.0462x over previous
#include <cuda_runtime.h>
#include <cuda_fp16.h>
#include <math.h>

#define DN   128
#define HK   65
#define BN   4
#define TN   2
#define GN   125
#define PERB (TN*GN)      // 250
#define NBTG (BN*PERB)    // 1000
#define WIN  24
#define H0   52
#define KT   9            // ceil(65/8) kx tiles
#define CP   130          // padded column stride for tile kernels
#define FCB  33           // blocks for fc premultiply: ceil(4*128*65/1024)
#define PSP  8            // plane sub-splits in kPack

// ---------------- scratch (static device memory; no allocation) ----------------
__device__ float2 g_vf[DN*DN*HK];       // vol rfft (float, built by 3 FFT passes)
__device__ uint4  g_vq[DN*DN*HK];       // fp16 corner-quad volume (17 MB)
__device__ float2 g_fimg[BN*DN*HK];     // image rffts, y fftshifted
__device__ float2 g_fc[BN*DN*HK];       // ctf*fimg*sign*alpha, (h,l) layout
__device__ float2 g_fcT[BN*HK*DN];      // same, transposed (l,h) layout
__device__ float2 g_G1[NBTG*DN*WIN];    // stage-1 results (24.6 MB)
__device__ float  g_corr[NBTG];
__device__ int    g_argm[NBTG];

__device__ __forceinline__ float2 cmulf(float2 a, float2 b){
    return make_float2(a.x*b.x - a.y*b.y, a.x*b.y + a.y*b.x);
}
__device__ __forceinline__ float2 cadd(float2 a, float2 b){ return make_float2(a.x+b.x, a.y+b.y); }
__device__ __forceinline__ float2 csub(float2 a, float2 b){ return make_float2(a.x-b.x, a.y-b.y); }
__device__ __forceinline__ int rev7(int p){ return (int)(__brev((unsigned)p) >> 25); }

__device__ __forceinline__ unsigned int f2h2(float2 v){
    __half2 h = __floats2half2_rn(v.x, v.y);
    return *reinterpret_cast<unsigned int*>(&h);
}
__device__ __forceinline__ float2 h2f2(unsigned int u){
    __half2 h = *reinterpret_cast<__half2*>(&u);
    return __half22float2(h);
}

__device__ __forceinline__ void make_tw(float2* Ef, int tid){
    if (tid < 128){
        float s, c;
        sincosf(-6.283185307179586f * (float)tid * (1.0f/128.0f), &s, &c);
        Ef[tid] = make_float2(c, s);
    }
}
__device__ __forceinline__ void make_twi(float2* Ei, int tid){
    if (tid < 128){
        float s, c;
        sincosf(6.283185307179586f * (float)tid * (1.0f/128.0f), &s, &c);
        Ei[tid] = make_float2(c, s);
    }
}

// shfl-xor DIF butterfly
__device__ __forceinline__ void bfx(float2& r, int mask, float2 tw, int lane){
    float ox = __shfl_xor_sync(0xffffffffu, r.x, mask);
    float oy = __shfl_xor_sync(0xffffffffu, r.y, mask);
    if ((lane & mask) == 0){ r.x += ox; r.y += oy; }
    else { float ux = ox - r.x, uy = oy - r.y; r = make_float2(ux*tw.x - uy*tw.y, ux*tw.y + uy*tw.x); }
}
__device__ __forceinline__ void bf1(float2& r, int lane){
    float ox = __shfl_xor_sync(0xffffffffu, r.x, 1);
    float oy = __shfl_xor_sync(0xffffffffu, r.y, 1);
    if ((lane & 1) == 0){ r.x += ox; r.y += oy; }
    else { r.x = ox - r.x; r.y = oy - r.y; }
}

// ---------------- warp-local smem 128-pt FFT (volume/image passes) -----------
__device__ __forceinline__ void fft128_w32(float2* col, const float2* Ef, int lane){
    for (int shift = 6; shift >= 0; shift--){
        int half = 1 << shift;
        int twsh = 6 - shift;
        #pragma unroll
        for (int k = 0; k < 2; k++){
            int bf   = lane + k*32;
            int j    = bf & (half - 1);
            int grp  = bf >> shift;
            int base = (grp << (shift + 1)) + j;
            float2 u = col[base];
            float2 v = col[base + half];
            float2 d = make_float2(u.x - v.x, u.y - v.y);
            col[base]        = make_float2(u.x + v.x, u.y + v.y);
            col[base + half] = cmulf(d, Ef[j << twsh]);
        }
        __syncwarp();
    }
    float2 r[4];
    #pragma unroll
    for (int k = 0; k < 4; k++) r[k] = col[lane + k*32];
    __syncwarp();
    #pragma unroll
    for (int k = 0; k < 4; k++){
        int y = lane + k*32;
        col[rev7(y)] = r[k];
    }
    __syncwarp();
}

// ---------------- pass 1: row rffts (vol rows + img rows), warp-per-row ------
__global__ void __launch_bounds__(256) kPre(const float* __restrict__ vol,
                                            const float* __restrict__ imgs){
    __shared__ float2 ws[8][128];
    __shared__ float2 Ef[128];
    int tid = threadIdx.x, wid = tid >> 5, lane = tid & 31;
    make_tw(Ef, tid);
    __syncthreads();
    float2* w = ws[wid];
    if (blockIdx.x < 2048){
        int row = blockIdx.x * 8 + wid;       // 0..16383
        int z = row >> 7, y = row & 127;
        float fz = (float)(z - 64) * (1.0f/128.0f);
        float fy = (float)(y - 64) * (1.0f/128.0f);
        float fzy = fz*fz + fy*fy;
        #pragma unroll
        for (int k = 0; k < 4; k++){
            int x = lane + k*32;
            float fx = (float)(x - 64) * (1.0f/128.0f);
            float r  = sqrtf(fzy + fx*fx);
            float wt;
            if (r < 1e-12f) wt = 1.0f;
            else { float pr = 3.14159265358979f * r; wt = __sinf(pr) / pr; }
            wt = wt * wt;
            w[(x + 64) & 127] = make_float2(vol[(z*DN + y)*DN + x] * wt, 0.0f);
        }
        __syncwarp();
        fft128_w32(w, Ef, lane);
        #pragma unroll
        for (int k = 0; k < 3; k++){
            int x = lane + k*32;
            if (x < HK) g_vf[(z*DN + y)*HK + x] = w[x];
        }
    } else {
        int row = (blockIdx.x - 2048) * 8 + wid;  // 0..511
        int b = row >> 7, r = row & 127;
        #pragma unroll
        for (int k = 0; k < 4; k++){
            int x = lane + k*32;
            w[(x + 64) & 127] = make_float2(imgs[(b*DN + r)*DN + x], 0.0f);
        }
        __syncwarp();
        fft128_w32(w, Ef, lane);
        #pragma unroll
        for (int k = 0; k < 3; k++){
            int x = lane + k*32;
            if (x < HK) g_fimg[(b*DN + r)*HK + x] = w[x];
        }
    }
}

// ---------------- pass 2: y-FFT tiles (vol planes + image planes), in place --
__global__ void __launch_bounds__(256) kMid(){
    __shared__ float2 a[8][CP];
    __shared__ float2 Ef[128];
    int tid = threadIdx.x;
    make_tw(Ef, tid);
    float2* base;
    int kt;
    if (blockIdx.x < DN*KT){
        int z = blockIdx.x / KT;
        kt = blockIdx.x % KT;
        base = g_vf + z*DN*HK;
    } else {
        int u = blockIdx.x - DN*KT;
        int b = u / KT;
        kt = u % KT;
        base = g_fimg + b*DN*HK;
    }
    int kx0 = kt * 8;
    #pragma unroll
    for (int k = 0; k < 4; k++){
        int idx = tid + k*256;
        int y = idx >> 3, c = idx & 7;
        int kx = kx0 + c;
        if (kx < HK){
            int ys = (y + 64) & 127;
            a[c][y] = base[ys*HK + kx];
        }
    }
    __syncthreads();
    int wid = tid >> 5, lane = tid & 31;
    if (kx0 + wid < HK) fft128_w32(a[wid], Ef, lane);
    __syncthreads();
    #pragma unroll
    for (int k = 0; k < 4; k++){
        int idx = tid + k*256;
        int y = idx >> 3, c = idx & 7;
        int kx = kx0 + c;
        if (kx < HK){
            int ys = (y + 64) & 127;
            base[ys*HK + kx] = a[c][y];
        }
    }
}

// ---------------- pass 3: z-FFT tiles on volume, in place --------------------
__global__ void __launch_bounds__(256) kVolZT(){
    __shared__ float2 a[8][CP];
    __shared__ float2 Ef[128];
    int tid = threadIdx.x;
    int sy  = blockIdx.x / KT;
    int kt  = blockIdx.x % KT;
    int kx0 = kt * 8;
    make_tw(Ef, tid);
    #pragma unroll
    for (int k = 0; k < 4; k++){
        int idx = tid + k*256;
        int zz = idx >> 3, c = idx & 7;
        int kx = kx0 + c;
        if (kx < HK){
            int zs = (zz + 64) & 127;
            a[c][zz] = g_vf[(zs*DN + sy)*HK + kx];
        }
    }
    __syncthreads();
    int wid = tid >> 5, lane = tid & 31;
    if (kx0 + wid < HK) fft128_w32(a[wid], Ef, lane);
    __syncthreads();
    #pragma unroll
    for (int k = 0; k < 4; k++){
        int idx = tid + k*256;
        int zz = idx >> 3, c = idx & 7;
        int kx = kx0 + c;
        if (kx < HK){
            int zs = (zz + 64) & 127;
            g_vf[(zs*DN + sy)*HK + kx] = a[c][zz];
        }
    }
}

// ---------------- pass 4: fp16 corner-quad volume + fc (both layouts) --------
// blocks [0, DN*PSP): plane-part quad pack; blocks [DN*PSP, +FCB): fc premultiply.
__global__ void __launch_bounds__(256) kPack(const float* __restrict__ ctf){
    if (blockIdx.x >= DN*PSP){
        int e0 = (blockIdx.x - DN*PSP) * 1024 + threadIdx.x * 4;
        #pragma unroll
        for (int k = 0; k < 4; k++){
            int e = e0 + k;
            if (e < BN*DN*HK){
                int l  = e % HK;
                int hb = e / HK;          // b*DN + h
                int h  = hb % DN;
                int b  = hb / DN;
                float sgn = ((h + l) & 1) ? -1.0f : 1.0f;
                if (l != 0 && l != 64) sgn *= 2.0f;
                float cf = __ldg(&ctf[e]) * sgn;
                float2 fi = g_fimg[e];
                float2 v = make_float2(fi.x*cf, fi.y*cf);
                g_fc[e] = v;
                g_fcT[(b*HK + l)*DN + h] = v;
            }
        }
        return;
    }
    int z    = blockIdx.x >> 3;          // PSP = 8
    int part = blockIdx.x & 7;
    const float2* pl = g_vf + z*DN*HK;
    int i0 = part * (DN*HK/PSP);         // 1040 per part
    int i1 = i0 + (DN*HK/PSP);
    for (int idx = i0 + threadIdx.x; idx < i1; idx += 256){
        int y = idx / HK;
        int x = idx - y*HK;
        float2 zero = make_float2(0.f, 0.f);
        float2 v00 = pl[y*HK + x];
        float2 v01 = (x+1 < HK) ? pl[y*HK + x + 1] : zero;
        float2 v10 = (y+1 < DN) ? pl[(y+1)*HK + x] : zero;
        float2 v11 = (y+1 < DN && x+1 < HK) ? pl[(y+1)*HK + x + 1] : zero;
        g_vq[(z*DN + y)*HK + x] = make_uint4(f2h2(v00), f2h2(v01), f2h2(v10), f2h2(v11));
    }
}

// ---------------- matcher stage A: quad gather + register iFFT ---------------
// one block per (bid, stripe): grid = NBTG*4
__global__ void __launch_bounds__(256) kMatchA(const float* __restrict__ rotm,
                                               const float* __restrict__ gridm){
    __shared__ float2 Pp[32][HK];     // product stripe
    __shared__ float2 wb[8][128];     // per-warp bitrev scratch
    __shared__ float2 Ei[128];        // exp(+2*pi*i*j/128)
    __shared__ float  Ac[3], Bc[3];

    int tid = threadIdx.x, wid = tid >> 5, lane = tid & 31;
    int bid    = blockIdx.x >> 2;
    int stripe = blockIdx.x & 3;
    int b  = bid / PERB;
    int rr = bid % PERB;
    int t  = rr / GN;
    int g  = rr % GN;
    int hbase = stripe * 32;

    make_twi(Ei, tid);
    if (tid < 3){
        int i  = tid;
        int ii = 2 - i;
        const float* R  = rotm  + ((b*TN + t)*3 + ii)*3;
        const float* Gm = gridm + g*9;
        Ac[i] = R[0]*Gm[1] + R[1]*Gm[4] + R[2]*Gm[7];
        Bc[i] = R[0]*Gm[0] + R[1]*Gm[3] + R[2]*Gm[6];
    }
    __syncthreads();
    float A0=Ac[0], A1=Ac[1], A2=Ac[2], B0=Bc[0], B1=Bc[1], B2=Bc[2];
    bool stepH = fabsf(A2) > fabsf(B2);   // lanes step along fastest-x direction

    float2 T1a = Ei[lane];
    float2 T1b = Ei[lane + 32];
    float2 T2  = Ei[2*lane];
    float2 T3  = Ei[(lane & 15)*4];
    float2 T4  = Ei[(lane & 7)*8];
    float2 T5  = Ei[(lane & 3)*16];
    float2 T6  = Ei[(lane & 1)*32];

    const float2* fcb  = g_fc  + b*DN*HK;
    const float2* fcTb = g_fcT + b*HK*DN;

    // ---- stage 0: slice extraction (2x16B quad loads per point) + product ----
    for (int idx = tid; idx < 32*HK; idx += 256){
        int hh, l;
        if (stepH){ l = idx >> 5; hh = idx & 31; }
        else      { hh = idx / HK; l = idx - hh*HK; }
        int h  = hbase + hh;
        float hm = (float)(h - 64);
        float lf = (float)l;
        float v0 = A0*hm + B0*lf;
        float v1 = A1*hm + B1*lf;
        float v2 = A2*hm + B2*lf;
        bool neg = (v2 < 0.0f);
        if (neg){ v0 = -v0; v1 = -v1; v2 = -v2; }
        float zc = v0 + 64.0f, yc = v1 + 64.0f, xc = v2;
        float zf = floorf(zc), yf = floorf(yc), xf = floorf(xc);
        int z0 = (int)zf, y0 = (int)yf, x0 = (int)xf;
        float fz = zc - zf, fy = yc - yf, fx = xc - xf;
        float2 acc = make_float2(0.0f, 0.0f);
        if (x0 < HK && z0 >= -1 && z0 < DN && y0 >= -1 && y0 < DN){
            float fx1 = 1.0f - fx;
            int   za  = (z0 >= 0)     ? z0     : 0;
            float wz0 = (z0 >= 0)     ? 1.0f - fz : 0.0f;
            int   zb  = (z0+1 < DN)   ? z0+1   : 0;
            float wz1 = (z0+1 < DN)   ? fz     : 0.0f;
            int   yq;  float wyA, wyB;
            if (y0 >= 0){ yq = y0; wyA = 1.0f - fy; wyB = fy; }
            else        { yq = 0;  wyA = fy;        wyB = 0.0f; }
            uint4 qA = __ldg(&g_vq[(za*DN + yq)*HK + x0]);
            uint4 qB = __ldg(&g_vq[(zb*DN + yq)*HK + x0]);
            float wA0 = wz0*wyA*fx1, wA1 = wz0*wyA*fx;
            float wA2 = wz0*wyB*fx1, wA3 = wz0*wyB*fx;
            float wB0 = wz1*wyA*fx1, wB1 = wz1*wyA*fx;
            float wB2 = wz1*wyB*fx1, wB3 = wz1*wyB*fx;
            float2 a00 = h2f2(qA.x), a01 = h2f2(qA.y), a10 = h2f2(qA.z), a11 = h2f2(qA.w);
            float2 b00 = h2f2(qB.x), b01 = h2f2(qB.y), b10 = h2f2(qB.z), b11 = h2f2(qB.w);
            acc.x = wA0*a00.x + wA1*a01.x + wA2*a10.x + wA3*a11.x
                  + wB0*b00.x + wB1*b01.x + wB2*b10.x + wB3*b11.x;
            acc.y = wA0*a00.y + wA1*a01.y + wA2*a10.y + wA3*a11.y
                  + wB0*b00.y + wB1*b01.y + wB2*b10.y + wB3*b11.y;
        }
        if (neg) acc.y = -acc.y;                 // conj
        float2 fi = stepH ? __ldg(&fcTb[l*DN + h])    // h-fast: coalesced in fcT
                          : __ldg(&fcb[h*HK + l]);    // l-fast: coalesced in fc
        Pp[hh][l] = make_float2(fi.x*acc.x + fi.y*acc.y,
                                fi.y*acc.x - fi.x*acc.y);
    }
    __syncthreads();

    // ---- stage 1: zero-padded 128-pt register inverse FFT per row -----------
    {
        float2* col = wb[wid];
        #pragma unroll
        for (int rr2 = 0; rr2 < 4; rr2++){
            int row = 4*wid + rr2;
            float2 r0 = Pp[row][lane];
            float2 r1 = Pp[row][lane + 32];
            float2 r2 = (lane == 0) ? Pp[row][64] : make_float2(0.f, 0.f);
            float2 r3;
            { float2 d = csub(r0, r2); r0 = cadd(r0, r2); r2 = cmulf(d, T1a);
              r3 = cmulf(r1, T1b); }
            { float2 d = csub(r0, r1); r0 = cadd(r0, r1); r1 = cmulf(d, T2);
              float2 e = csub(r2, r3); r2 = cadd(r2, r3); r3 = cmulf(e, T2); }
            bfx(r0, 16, T3, lane); bfx(r1, 16, T3, lane); bfx(r2, 16, T3, lane); bfx(r3, 16, T3, lane);
            bfx(r0,  8, T4, lane); bfx(r1,  8, T4, lane); bfx(r2,  8, T4, lane); bfx(r3,  8, T4, lane);
            bfx(r0,  4, T5, lane); bfx(r1,  4, T5, lane); bfx(r2,  4, T5, lane); bfx(r3,  4, T5, lane);
            bfx(r0,  2, T6, lane); bfx(r1,  2, T6, lane); bfx(r2,  2, T6, lane); bfx(r3,  2, T6, lane);
            bf1(r0, lane); bf1(r1, lane); bf1(r2, lane); bf1(r3, lane);
            col[rev7(lane      )] = r0;
            col[rev7(lane + 32 )] = r1;
            col[rev7(lane + 64 )] = r2;
            col[rev7(lane + 96 )] = r3;
            __syncwarp();
            if (lane < WIN)
                g_G1[(bid*DN + hbase + row)*WIN + lane] = col[H0 + lane];
            __syncwarp();
        }
    }
}

// ---------------- matcher stage B: register iFFT per column + argmax ---------
__global__ void __launch_bounds__(256) kMatchB(){
    __shared__ float2 G1s[DN][WIN+1];
    __shared__ float  wbf[8][128];
    __shared__ float2 Ei[128];
    __shared__ float  rv[256];
    __shared__ int    ri[256];
    int tid = threadIdx.x, wid = tid >> 5, lane = tid & 31;
    int bid = blockIdx.x;

    make_twi(Ei, tid);
    const float2* src = g_G1 + bid*DN*WIN;
    for (int idx = tid; idx < DN*WIN; idx += 256)
        G1s[idx / WIN][idx % WIN] = src[idx];
    __syncthreads();

    float2 T1a = Ei[lane];
    float2 T1b = Ei[lane + 32];
    float2 T2  = Ei[2*lane];
    float2 T3  = Ei[(lane & 15)*4];
    float2 T4  = Ei[(lane & 7)*8];
    float2 T5  = Ei[(lane & 3)*16];
    float2 T6  = Ei[(lane & 1)*32];

    float best = -3.4e38f;
    int bestIdx = 0x7fffffff;
    {
        float* colf = wbf[wid];
        #pragma unroll
        for (int j = 0; j < 3; j++){
            int v = 3*wid + j;
            float2 r0 = G1s[lane      ][v];
            float2 r1 = G1s[lane + 32 ][v];
            float2 r2 = G1s[lane + 64 ][v];
            float2 r3 = G1s[lane + 96 ][v];
            { float2 d = csub(r0, r2); r0 = cadd(r0, r2); r2 = cmulf(d, T1a);
              float2 e = csub(r1, r3); r1 = cadd(r1, r3); r3 = cmulf(e, T1b); }
            { float2 d = csub(r0, r1); r0 = cadd(r0, r1); r1 = cmulf(d, T2);
              float2 e = csub(r2, r3); r2 = cadd(r2, r3); r3 = cmulf(e, T2); }
            bfx(r0, 16, T3, lane); bfx(r1, 16, T3, lane); bfx(r2, 16, T3, lane); bfx(r3, 16, T3, lane);
            bfx(r0,  8, T4, lane); bfx(r1,  8, T4, lane); bfx(r2,  8, T4, lane); bfx(r3,  8, T4, lane);
            bfx(r0,  4, T5, lane); bfx(r1,  4, T5, lane); bfx(r2,  4, T5, lane); bfx(r3,  4, T5, lane);
            bfx(r0,  2, T6, lane); bfx(r1,  2, T6, lane); bfx(r2,  2, T6, lane); bfx(r3,  2, T6, lane);
            bf1(r0, lane); bf1(r1, lane); bf1(r2, lane); bf1(r3, lane);
            colf[rev7(lane      )] = r0.x;
            colf[rev7(lane + 32 )] = r1.x;
            colf[rev7(lane + 64 )] = r2.x;
            colf[rev7(lane + 96 )] = r3.x;
            __syncwarp();
            if (lane < WIN){
                int u = lane;
                float val = colf[H0 + u] * (1.0f/16384.0f);
                if (u & 1) val = -val;               // (-1)^(52+u)
                int idx = u*WIN + v;
                if (val > best || (val == best && idx < bestIdx)){ best = val; bestIdx = idx; }
            }
            __syncwarp();
        }
    }
    rv[tid] = best; ri[tid] = bestIdx;
    __syncthreads();
    for (int s = 128; s; s >>= 1){
        if (tid < s){
            float v2 = rv[tid+s]; int i2 = ri[tid+s];
            if (v2 > rv[tid] || (v2 == rv[tid] && i2 < ri[tid])){ rv[tid] = v2; ri[tid] = i2; }
        }
        __syncthreads();
    }
    if (tid == 0){ g_corr[bid] = rv[0]; g_argm[bid] = ri[0]; }
}

// ---------------- final per-batch reduction ----------------
__global__ void __launch_bounds__(256) kReduce(const float* __restrict__ gridm,
                                               float* __restrict__ out){
    __shared__ float sv[256];
    __shared__ int   si[256];
    __shared__ float s_mean, s_std;
    __shared__ float s_val[2];
    __shared__ int   s_idx[2];
    int b = blockIdx.x, tid = threadIdx.x;
    float v = (tid < PERB) ? g_corr[b*PERB + tid] : 0.0f;

    sv[tid] = (tid < PERB) ? v : 0.0f;
    __syncthreads();
    for (int s = 128; s; s >>= 1){ if (tid < s) sv[tid] += sv[tid+s]; __syncthreads(); }
    if (tid == 0) s_mean = sv[0] / (float)PERB;
    __syncthreads();
    float mean = s_mean;
    float d = (tid < PERB) ? (v - mean) : 0.0f;
    sv[tid] = d * d;
    __syncthreads();
    for (int s = 128; s; s >>= 1){ if (tid < s) sv[tid] += sv[tid+s]; __syncthreads(); }
    if (tid == 0) s_std = sqrtf(sv[0] / (float)(PERB - 1));
    __syncthreads();
    float stdv = s_std;

    for (int k = 0; k < 2; k++){
        bool excl = (k == 1 && tid == s_idx[0]);
        sv[tid] = (tid < PERB && !excl) ? v : -3.4e38f;
        si[tid] = tid;
        __syncthreads();
        for (int s = 128; s; s >>= 1){
            if (tid < s){
                float v2 = sv[tid+s]; int i2 = si[tid+s];
                if (v2 > sv[tid] || (v2 == sv[tid] && i2 < si[tid])){ sv[tid] = v2; si[tid] = i2; }
            }
            __syncthreads();
        }
        if (tid == 0){ s_val[k] = sv[0]; s_idx[k] = si[0]; }
        __syncthreads();
    }

    if (tid < 2){
        int k = tid;
        float val = s_val[k];
        int   idx = s_idx[k];
        int   gg  = idx % GN;
        int   a   = g_argm[b*PERB + idx];
        int   u   = a / WIN;
        int   vv  = a - u*WIN;
        int slot  = b*2 + k;
        out[slot] = val;
        for (int j = 0; j < 9; j++) out[8 + slot*9 + j] = gridm[gg*9 + j];
        out[80 + slot*2 + 0] = -((float)(H0 + vv) - 64.0f) * 1.5f;
        out[80 + slot*2 + 1] = -((float)(H0 + u)  - 64.0f) * 1.5f;
        float zz = (val - mean) / (stdv * 1.41421356237f);
        out[96 + slot] = 0.5f * (1.0f + erff(zz));
    }
}

// ---------------- launch ----------------
extern "C" void kernel_launch(void* const* d_in, const int* in_sizes, int n_in,
                              void* d_out, int out_size){
    const float* vol   = (const float*)d_in[0];
    const float* imgs  = (const float*)d_in[1];
    const float* ctf   = (const float*)d_in[2];
    const float* rotm  = (const float*)d_in[3];
    const float* gridm = (const float*)d_in[4];

    kPre<<<2112, 256>>>(vol, imgs);              // launch 1: vol-X + img rows
    kMid<<<DN*KT + BN*KT, 256>>>();              // launch 2: vol-Y + img cols
    kVolZT<<<DN*KT, 256>>>();                    // launch 3: vol-Z in place
    kPack<<<DN*PSP + FCB, 256>>>(ctf);           // launch 4: quads + fc(2 layouts)
    kMatchA<<<NBTG*4, 256>>>(rotm, gridm);       // launch 5
    kMatchB<<<NBTG, 256>>>();                    // launch 6
    kReduce<<<BN, 256>>>(gridm, (float*)d_out);  // launch 7
}

// round 17
// speedup vs baseline: 1.1535x; 1.0188x over previous
#include <cuda_runtime.h>
#include <cuda_fp16.h>
#include <math.h>

#define DN   128
#define HK   65
#define BN   4
#define TN   2
#define GN   125
#define PERB (TN*GN)      // 250
#define NBTG (BN*PERB)    // 1000
#define WIN  24
#define H0   52
#define KT   9            // ceil(65/8) kx tiles
#define CP   130          // padded column stride for tile kernels
#define FCB  33           // blocks for fc premultiply: ceil(4*128*65/1024)

// ---------------- scratch (static device memory; no allocation) ----------------
__device__ float2 g_vf[DN*DN*HK];       // vol rfft intermediate (x/y passes)
__device__ uint4  g_vq[DN*DN*HK];       // fp16 corner-quad volume (17 MB); ghost
                                        // slots rely on zero-init of device globals
__device__ float2 g_fimg[BN*DN*HK];     // image rffts, y fftshifted
__device__ float2 g_fc[BN*DN*HK];       // ctf*fimg*sign*alpha, (h,l) layout
__device__ float2 g_fcT[BN*HK*DN];      // same, transposed (l,h) layout
__device__ float2 g_G1[NBTG*DN*WIN];    // stage-1 results (24.6 MB)
__device__ float  g_corr[NBTG];
__device__ int    g_argm[NBTG];

__device__ __forceinline__ float2 cmulf(float2 a, float2 b){
    return make_float2(a.x*b.x - a.y*b.y, a.x*b.y + a.y*b.x);
}
__device__ __forceinline__ float2 cadd(float2 a, float2 b){ return make_float2(a.x+b.x, a.y+b.y); }
__device__ __forceinline__ float2 csub(float2 a, float2 b){ return make_float2(a.x-b.x, a.y-b.y); }
__device__ __forceinline__ int rev7(int p){ return (int)(__brev((unsigned)p) >> 25); }

__device__ __forceinline__ unsigned int f2h2(float2 v){
    __half2 h = __floats2half2_rn(v.x, v.y);
    return *reinterpret_cast<unsigned int*>(&h);
}
__device__ __forceinline__ float2 h2f2(unsigned int u){
    __half2 h = *reinterpret_cast<__half2*>(&u);
    return __half22float2(h);
}

__device__ __forceinline__ void make_tw(float2* Ef, int tid){
    if (tid < 128){
        float s, c;
        sincosf(-6.283185307179586f * (float)tid * (1.0f/128.0f), &s, &c);
        Ef[tid] = make_float2(c, s);
    }
}
__device__ __forceinline__ void make_twi(float2* Ei, int tid){
    if (tid < 128){
        float s, c;
        sincosf(6.283185307179586f * (float)tid * (1.0f/128.0f), &s, &c);
        Ei[tid] = make_float2(c, s);
    }
}

// shfl-xor DIF butterfly
__device__ __forceinline__ void bfx(float2& r, int mask, float2 tw, int lane){
    float ox = __shfl_xor_sync(0xffffffffu, r.x, mask);
    float oy = __shfl_xor_sync(0xffffffffu, r.y, mask);
    if ((lane & mask) == 0){ r.x += ox; r.y += oy; }
    else { float ux = ox - r.x, uy = oy - r.y; r = make_float2(ux*tw.x - uy*tw.y, ux*tw.y + uy*tw.x); }
}
__device__ __forceinline__ void bf1(float2& r, int lane){
    float ox = __shfl_xor_sync(0xffffffffu, r.x, 1);
    float oy = __shfl_xor_sync(0xffffffffu, r.y, 1);
    if ((lane & 1) == 0){ r.x += ox; r.y += oy; }
    else { r.x = ox - r.x; r.y = oy - r.y; }
}

// ---------------- warp-local smem 128-pt FFT (volume/image passes) -----------
__device__ __forceinline__ void fft128_w32(float2* col, const float2* Ef, int lane){
    for (int shift = 6; shift >= 0; shift--){
        int half = 1 << shift;
        int twsh = 6 - shift;
        #pragma unroll
        for (int k = 0; k < 2; k++){
            int bf   = lane + k*32;
            int j    = bf & (half - 1);
            int grp  = bf >> shift;
            int base = (grp << (shift + 1)) + j;
            float2 u = col[base];
            float2 v = col[base + half];
            float2 d = make_float2(u.x - v.x, u.y - v.y);
            col[base]        = make_float2(u.x + v.x, u.y + v.y);
            col[base + half] = cmulf(d, Ef[j << twsh]);
        }
        __syncwarp();
    }
    float2 r[4];
    #pragma unroll
    for (int k = 0; k < 4; k++) r[k] = col[lane + k*32];
    __syncwarp();
    #pragma unroll
    for (int k = 0; k < 4; k++){
        int y = lane + k*32;
        col[rev7(y)] = r[k];
    }
    __syncwarp();
}

// ---------------- pass 1: row rffts (vol rows + img rows), warp-per-row ------
__global__ void __launch_bounds__(256) kPre(const float* __restrict__ vol,
                                            const float* __restrict__ imgs){
    __shared__ float2 ws[8][128];
    __shared__ float2 Ef[128];
    int tid = threadIdx.x, wid = tid >> 5, lane = tid & 31;
    make_tw(Ef, tid);
    __syncthreads();
    float2* w = ws[wid];
    if (blockIdx.x < 2048){
        int row = blockIdx.x * 8 + wid;       // 0..16383
        int z = row >> 7, y = row & 127;
        float fz = (float)(z - 64) * (1.0f/128.0f);
        float fy = (float)(y - 64) * (1.0f/128.0f);
        float fzy = fz*fz + fy*fy;
        #pragma unroll
        for (int k = 0; k < 4; k++){
            int x = lane + k*32;
            float fx = (float)(x - 64) * (1.0f/128.0f);
            float r  = sqrtf(fzy + fx*fx);
            float wt;
            if (r < 1e-12f) wt = 1.0f;
            else { float pr = 3.14159265358979f * r; wt = __sinf(pr) / pr; }
            wt = wt * wt;
            w[(x + 64) & 127] = make_float2(vol[(z*DN + y)*DN + x] * wt, 0.0f);
        }
        __syncwarp();
        fft128_w32(w, Ef, lane);
        #pragma unroll
        for (int k = 0; k < 3; k++){
            int x = lane + k*32;
            if (x < HK) g_vf[(z*DN + y)*HK + x] = w[x];
        }
    } else {
        int row = (blockIdx.x - 2048) * 8 + wid;  // 0..511
        int b = row >> 7, r = row & 127;
        #pragma unroll
        for (int k = 0; k < 4; k++){
            int x = lane + k*32;
            w[(x + 64) & 127] = make_float2(imgs[(b*DN + r)*DN + x], 0.0f);
        }
        __syncwarp();
        fft128_w32(w, Ef, lane);
        #pragma unroll
        for (int k = 0; k < 3; k++){
            int x = lane + k*32;
            if (x < HK) g_fimg[(b*DN + r)*HK + x] = w[x];
        }
    }
}

// ---------------- pass 2: y-FFT tiles (vol planes + image planes), in place --
__global__ void __launch_bounds__(256) kMid(){
    __shared__ float2 a[8][CP];
    __shared__ float2 Ef[128];
    int tid = threadIdx.x;
    make_tw(Ef, tid);
    float2* base;
    int kt;
    if (blockIdx.x < DN*KT){
        int z = blockIdx.x / KT;
        kt = blockIdx.x % KT;
        base = g_vf + z*DN*HK;
    } else {
        int u = blockIdx.x - DN*KT;
        int b = u / KT;
        kt = u % KT;
        base = g_fimg + b*DN*HK;
    }
    int kx0 = kt * 8;
    #pragma unroll
    for (int k = 0; k < 4; k++){
        int idx = tid + k*256;
        int y = idx >> 3, c = idx & 7;
        int kx = kx0 + c;
        if (kx < HK){
            int ys = (y + 64) & 127;
            a[c][y] = base[ys*HK + kx];
        }
    }
    __syncthreads();
    int wid = tid >> 5, lane = tid & 31;
    if (kx0 + wid < HK) fft128_w32(a[wid], Ef, lane);
    __syncthreads();
    #pragma unroll
    for (int k = 0; k < 4; k++){
        int idx = tid + k*256;
        int y = idx >> 3, c = idx & 7;
        int kx = kx0 + c;
        if (kx < HK){
            int ys = (y + 64) & 127;
            base[ys*HK + kx] = a[c][y];
        }
    }
}

// ---------------- pass 3: z-FFT tiles; scatter-pack fp16 quads; fc blocks ----
// blocks [0, DN*KT): vol z-FFT + quad scatter; blocks [DN*KT, +FCB): fc.
__global__ void __launch_bounds__(256) kVolZT(const float* __restrict__ ctf){
    if (blockIdx.x >= DN*KT){
        // fc premultiply (both layouts); g_fimg is final after kMid
        int e0 = (blockIdx.x - DN*KT) * 1024 + threadIdx.x * 4;
        #pragma unroll
        for (int k = 0; k < 4; k++){
            int e = e0 + k;
            if (e < BN*DN*HK){
                int l  = e % HK;
                int hb = e / HK;          // b*DN + h
                int h  = hb % DN;
                int b  = hb / DN;
                float sgn = ((h + l) & 1) ? -1.0f : 1.0f;
                if (l != 0 && l != 64) sgn *= 2.0f;
                float cf = __ldg(&ctf[e]) * sgn;
                float2 fi = g_fimg[e];
                float2 v = make_float2(fi.x*cf, fi.y*cf);
                g_fc[e] = v;
                g_fcT[(b*HK + l)*DN + h] = v;
            }
        }
        return;
    }
    __shared__ float2 a[8][CP];
    __shared__ float2 Ef[128];
    int tid = threadIdx.x;
    int sy  = blockIdx.x / KT;
    int kt  = blockIdx.x % KT;
    int kx0 = kt * 8;
    make_tw(Ef, tid);
    #pragma unroll
    for (int k = 0; k < 4; k++){
        int idx = tid + k*256;
        int zz = idx >> 3, c = idx & 7;
        int kx = kx0 + c;
        if (kx < HK){
            int zs = (zz + 64) & 127;
            a[c][zz] = g_vf[(zs*DN + sy)*HK + kx];
        }
    }
    __syncthreads();
    int wid = tid >> 5, lane = tid & 31;
    if (kx0 + wid < HK) fft128_w32(a[wid], Ef, lane);
    __syncthreads();
    // scatter each final value into the <=4 quad slots that reference it.
    // Ghost slots (y==128 row, x==65 col) are never written -> stay zero (init).
    unsigned int* vq = (unsigned int*)g_vq;
    #pragma unroll
    for (int k = 0; k < 4; k++){
        int idx = tid + k*256;
        int zz = idx >> 3, c = idx & 7;
        int kx = kx0 + c;
        if (kx < HK){
            int zs = (zz + 64) & 127;
            unsigned int val = f2h2(a[c][zz]);
            int rowbase = (zs*DN + sy)*HK;
            vq[4*(rowbase + kx) + 0] = val;                       // v00 of (sy,kx)
            if (kx > 0) vq[4*(rowbase + kx - 1) + 1] = val;       // v01 of (sy,kx-1)
            if (sy > 0){
                int rb2 = rowbase - HK;                           // (sy-1) row
                vq[4*(rb2 + kx) + 2] = val;                       // v10 of (sy-1,kx)
                if (kx > 0) vq[4*(rb2 + kx - 1) + 3] = val;       // v11 of (sy-1,kx-1)
            }
        }
    }
}

// ---------------- matcher stage A: quad gather + register iFFT ---------------
// one block per (bid, stripe): grid = NBTG*4
__global__ void __launch_bounds__(256) kMatchA(const float* __restrict__ rotm,
                                               const float* __restrict__ gridm){
    __shared__ float2 Pp[32][HK];     // product stripe
    __shared__ float2 wb[8][128];     // per-warp bitrev scratch
    __shared__ float2 Ei[128];        // exp(+2*pi*i*j/128)
    __shared__ float  Ac[3], Bc[3];

    int tid = threadIdx.x, wid = tid >> 5, lane = tid & 31;
    int bid    = blockIdx.x >> 2;
    int stripe = blockIdx.x & 3;
    int b  = bid / PERB;
    int rr = bid % PERB;
    int t  = rr / GN;
    int g  = rr % GN;
    int hbase = stripe * 32;

    make_twi(Ei, tid);
    if (tid < 3){
        int i  = tid;
        int ii = 2 - i;
        const float* R  = rotm  + ((b*TN + t)*3 + ii)*3;
        const float* Gm = gridm + g*9;
        Ac[i] = R[0]*Gm[1] + R[1]*Gm[4] + R[2]*Gm[7];
        Bc[i] = R[0]*Gm[0] + R[1]*Gm[3] + R[2]*Gm[6];
    }
    __syncthreads();
    float A0=Ac[0], A1=Ac[1], A2=Ac[2], B0=Bc[0], B1=Bc[1], B2=Bc[2];
    bool stepH = fabsf(A2) > fabsf(B2);   // lanes step along fastest-x direction

    float2 T1a = Ei[lane];
    float2 T1b = Ei[lane + 32];
    float2 T2  = Ei[2*lane];
    float2 T3  = Ei[(lane & 15)*4];
    float2 T4  = Ei[(lane & 7)*8];
    float2 T5  = Ei[(lane & 3)*16];
    float2 T6  = Ei[(lane & 1)*32];

    const float2* fcb  = g_fc  + b*DN*HK;
    const float2* fcTb = g_fcT + b*HK*DN;

    // ---- stage 0: slice extraction (2x16B quad loads per point) + product ----
    for (int idx = tid; idx < 32*HK; idx += 256){
        int hh, l;
        if (stepH){ l = idx >> 5; hh = idx & 31; }
        else      { hh = idx / HK; l = idx - hh*HK; }
        int h  = hbase + hh;
        float hm = (float)(h - 64);
        float lf = (float)l;
        float v0 = A0*hm + B0*lf;
        float v1 = A1*hm + B1*lf;
        float v2 = A2*hm + B2*lf;
        bool neg = (v2 < 0.0f);
        if (neg){ v0 = -v0; v1 = -v1; v2 = -v2; }
        float zc = v0 + 64.0f, yc = v1 + 64.0f, xc = v2;
        float zf = floorf(zc), yf = floorf(yc), xf = floorf(xc);
        int z0 = (int)zf, y0 = (int)yf, x0 = (int)xf;
        float fz = zc - zf, fy = yc - yf, fx = xc - xf;
        float2 acc = make_float2(0.0f, 0.0f);
        if (x0 < HK && z0 >= -1 && z0 < DN && y0 >= -1 && y0 < DN){
            float fx1 = 1.0f - fx;
            int   za  = (z0 >= 0)     ? z0     : 0;
            float wz0 = (z0 >= 0)     ? 1.0f - fz : 0.0f;
            int   zb  = (z0+1 < DN)   ? z0+1   : 0;
            float wz1 = (z0+1 < DN)   ? fz     : 0.0f;
            int   yq;  float wyA, wyB;
            if (y0 >= 0){ yq = y0; wyA = 1.0f - fy; wyB = fy; }
            else        { yq = 0;  wyA = fy;        wyB = 0.0f; }
            uint4 qA = __ldg(&g_vq[(za*DN + yq)*HK + x0]);
            uint4 qB = __ldg(&g_vq[(zb*DN + yq)*HK + x0]);
            float wA0 = wz0*wyA*fx1, wA1 = wz0*wyA*fx;
            float wA2 = wz0*wyB*fx1, wA3 = wz0*wyB*fx;
            float wB0 = wz1*wyA*fx1, wB1 = wz1*wyA*fx;
            float wB2 = wz1*wyB*fx1, wB3 = wz1*wyB*fx;
            float2 a00 = h2f2(qA.x), a01 = h2f2(qA.y), a10 = h2f2(qA.z), a11 = h2f2(qA.w);
            float2 b00 = h2f2(qB.x), b01 = h2f2(qB.y), b10 = h2f2(qB.z), b11 = h2f2(qB.w);
            acc.x = wA0*a00.x + wA1*a01.x + wA2*a10.x + wA3*a11.x
                  + wB0*b00.x + wB1*b01.x + wB2*b10.x + wB3*b11.x;
            acc.y = wA0*a00.y + wA1*a01.y + wA2*a10.y + wA3*a11.y
                  + wB0*b00.y + wB1*b01.y + wB2*b10.y + wB3*b11.y;
        }
        if (neg) acc.y = -acc.y;                 // conj
        float2 fi = stepH ? __ldg(&fcTb[l*DN + h])    // h-fast: coalesced in fcT
                          : __ldg(&fcb[h*HK + l]);    // l-fast: coalesced in fc
        Pp[hh][l] = make_float2(fi.x*acc.x + fi.y*acc.y,
                                fi.y*acc.x - fi.x*acc.y);
    }
    __syncthreads();

    // ---- stage 1: zero-padded 128-pt register inverse FFT per row -----------
    {
        float2* col = wb[wid];
        #pragma unroll
        for (int rr2 = 0; rr2 < 4; rr2++){
            int row = 4*wid + rr2;
            float2 r0 = Pp[row][lane];
            float2 r1 = Pp[row][lane + 32];
            float2 r2 = (lane == 0) ? Pp[row][64] : make_float2(0.f, 0.f);
            float2 r3;
            { float2 d = csub(r0, r2); r0 = cadd(r0, r2); r2 = cmulf(d, T1a);
              r3 = cmulf(r1, T1b); }
            { float2 d = csub(r0, r1); r0 = cadd(r0, r1); r1 = cmulf(d, T2);
              float2 e = csub(r2, r3); r2 = cadd(r2, r3); r3 = cmulf(e, T2); }
            bfx(r0, 16, T3, lane); bfx(r1, 16, T3, lane); bfx(r2, 16, T3, lane); bfx(r3, 16, T3, lane);
            bfx(r0,  8, T4, lane); bfx(r1,  8, T4, lane); bfx(r2,  8, T4, lane); bfx(r3,  8, T4, lane);
            bfx(r0,  4, T5, lane); bfx(r1,  4, T5, lane); bfx(r2,  4, T5, lane); bfx(r3,  4, T5, lane);
            bfx(r0,  2, T6, lane); bfx(r1,  2, T6, lane); bfx(r2,  2, T6, lane); bfx(r3,  2, T6, lane);
            bf1(r0, lane); bf1(r1, lane); bf1(r2, lane); bf1(r3, lane);
            col[rev7(lane      )] = r0;
            col[rev7(lane + 32 )] = r1;
            col[rev7(lane + 64 )] = r2;
            col[rev7(lane + 96 )] = r3;
            __syncwarp();
            if (lane < WIN)
                g_G1[(bid*DN + hbase + row)*WIN + lane] = col[H0 + lane];
            __syncwarp();
        }
    }
}

// ---------------- matcher stage B: register iFFT per column + argmax ---------
__global__ void __launch_bounds__(256) kMatchB(){
    __shared__ float2 G1s[DN][WIN+1];
    __shared__ float  wbf[8][128];
    __shared__ float2 Ei[128];
    __shared__ float  rv[256];
    __shared__ int    ri[256];
    int tid = threadIdx.x, wid = tid >> 5, lane = tid & 31;
    int bid = blockIdx.x;

    make_twi(Ei, tid);
    const float2* src = g_G1 + bid*DN*WIN;
    for (int idx = tid; idx < DN*WIN; idx += 256)
        G1s[idx / WIN][idx % WIN] = src[idx];
    __syncthreads();

    float2 T1a = Ei[lane];
    float2 T1b = Ei[lane + 32];
    float2 T2  = Ei[2*lane];
    float2 T3  = Ei[(lane & 15)*4];
    float2 T4  = Ei[(lane & 7)*8];
    float2 T5  = Ei[(lane & 3)*16];
    float2 T6  = Ei[(lane & 1)*32];

    float best = -3.4e38f;
    int bestIdx = 0x7fffffff;
    {
        float* colf = wbf[wid];
        #pragma unroll
        for (int j = 0; j < 3; j++){
            int v = 3*wid + j;
            float2 r0 = G1s[lane      ][v];
            float2 r1 = G1s[lane + 32 ][v];
            float2 r2 = G1s[lane + 64 ][v];
            float2 r3 = G1s[lane + 96 ][v];
            { float2 d = csub(r0, r2); r0 = cadd(r0, r2); r2 = cmulf(d, T1a);
              float2 e = csub(r1, r3); r1 = cadd(r1, r3); r3 = cmulf(e, T1b); }
            { float2 d = csub(r0, r1); r0 = cadd(r0, r1); r1 = cmulf(d, T2);
              float2 e = csub(r2, r3); r2 = cadd(r2, r3); r3 = cmulf(e, T2); }
            bfx(r0, 16, T3, lane); bfx(r1, 16, T3, lane); bfx(r2, 16, T3, lane); bfx(r3, 16, T3, lane);
            bfx(r0,  8, T4, lane); bfx(r1,  8, T4, lane); bfx(r2,  8, T4, lane); bfx(r3,  8, T4, lane);
            bfx(r0,  4, T5, lane); bfx(r1,  4, T5, lane); bfx(r2,  4, T5, lane); bfx(r3,  4, T5, lane);
            bfx(r0,  2, T6, lane); bfx(r1,  2, T6, lane); bfx(r2,  2, T6, lane); bfx(r3,  2, T6, lane);
            bf1(r0, lane); bf1(r1, lane); bf1(r2, lane); bf1(r3, lane);
            colf[rev7(lane      )] = r0.x;
            colf[rev7(lane + 32 )] = r1.x;
            colf[rev7(lane + 64 )] = r2.x;
            colf[rev7(lane + 96 )] = r3.x;
            __syncwarp();
            if (lane < WIN){
                int u = lane;
                float val = colf[H0 + u] * (1.0f/16384.0f);
                if (u & 1) val = -val;               // (-1)^(52+u)
                int idx = u*WIN + v;
                if (val > best || (val == best && idx < bestIdx)){ best = val; bestIdx = idx; }
            }
            __syncwarp();
        }
    }
    rv[tid] = best; ri[tid] = bestIdx;
    __syncthreads();
    for (int s = 128; s; s >>= 1){
        if (tid < s){
            float v2 = rv[tid+s]; int i2 = ri[tid+s];
            if (v2 > rv[tid] || (v2 == rv[tid] && i2 < ri[tid])){ rv[tid] = v2; ri[tid] = i2; }
        }
        __syncthreads();
    }
    if (tid == 0){ g_corr[bid] = rv[0]; g_argm[bid] = ri[0]; }
}

// ---------------- final per-batch reduction ----------------
__global__ void __launch_bounds__(256) kReduce(const float* __restrict__ gridm,
                                               float* __restrict__ out){
    __shared__ float sv[256];
    __shared__ int   si[256];
    __shared__ float s_mean, s_std;
    __shared__ float s_val[2];
    __shared__ int   s_idx[2];
    int b = blockIdx.x, tid = threadIdx.x;
    float v = (tid < PERB) ? g_corr[b*PERB + tid] : 0.0f;

    sv[tid] = (tid < PERB) ? v : 0.0f;
    __syncthreads();
    for (int s = 128; s; s >>= 1){ if (tid < s) sv[tid] += sv[tid+s]; __syncthreads(); }
    if (tid == 0) s_mean = sv[0] / (float)PERB;
    __syncthreads();
    float mean = s_mean;
    float d = (tid < PERB) ? (v - mean) : 0.0f;
    sv[tid] = d * d;
    __syncthreads();
    for (int s = 128; s; s >>= 1){ if (tid < s) sv[tid] += sv[tid+s]; __syncthreads(); }
    if (tid == 0) s_std = sqrtf(sv[0] / (float)(PERB - 1));
    __syncthreads();
    float stdv = s_std;

    for (int k = 0; k < 2; k++){
        bool excl = (k == 1 && tid == s_idx[0]);
        sv[tid] = (tid < PERB && !excl) ? v : -3.4e38f;
        si[tid] = tid;
        __syncthreads();
        for (int s = 128; s; s >>= 1){
            if (tid < s){
                float v2 = sv[tid+s]; int i2 = si[tid+s];
                if (v2 > sv[tid] || (v2 == sv[tid] && i2 < si[tid])){ sv[tid] = v2; si[tid] = i2; }
            }
            __syncthreads();
        }
        if (tid == 0){ s_val[k] = sv[0]; s_idx[k] = si[0]; }
        __syncthreads();
    }

    if (tid < 2){
        int k = tid;
        float val = s_val[k];
        int   idx = s_idx[k];
        int   gg  = idx % GN;
        int   a   = g_argm[b*PERB + idx];
        int   u   = a / WIN;
        int   vv  = a - u*WIN;
        int slot  = b*2 + k;
        out[slot] = val;
        for (int j = 0; j < 9; j++) out[8 + slot*9 + j] = gridm[gg*9 + j];
        out[80 + slot*2 + 0] = -((float)(H0 + vv) - 64.0f) * 1.5f;
        out[80 + slot*2 + 1] = -((float)(H0 + u)  - 64.0f) * 1.5f;
        float zz = (val - mean) / (stdv * 1.41421356237f);
        out[96 + slot] = 0.5f * (1.0f + erff(zz));
    }
}

// ---------------- launch ----------------
extern "C" void kernel_launch(void* const* d_in, const int* in_sizes, int n_in,
                              void* d_out, int out_size){
    const float* vol   = (const float*)d_in[0];
    const float* imgs  = (const float*)d_in[1];
    const float* ctf   = (const float*)d_in[2];
    const float* rotm  = (const float*)d_in[3];
    const float* gridm = (const float*)d_in[4];

    kPre<<<2112, 256>>>(vol, imgs);              // launch 1: vol-X + img rows
    kMid<<<DN*KT + BN*KT, 256>>>();              // launch 2: vol-Y + img cols
    kVolZT<<<DN*KT + FCB, 256>>>(ctf);           // launch 3: vol-Z + quad pack + fc
    kMatchA<<<NBTG*4, 256>>>(rotm, gridm);       // launch 4  <- profiled
    kMatchB<<<NBTG, 256>>>();                    // launch 5
    kReduce<<<BN, 256>>>(gridm, (float*)d_out);  // launch 6
}